// round 3
// baseline (speedup 1.0000x reference)
#include <cuda_runtime.h>

#define B_ 4
#define S_ 2048
#define D_ 1024
#define H_ 16
#define HD_ 64
#define OUT_ 256
#define M_ (B_*S_)   // 8192
#define BH_ (B_*H_)  // 64

// Scratch (static device globals — no allocation allowed)
__device__ float g_Q[(size_t)BH_*S_*HD_];   // [BH][S][HD]
__device__ float g_K[(size_t)BH_*S_*HD_];
__device__ float g_V[(size_t)BH_*S_*HD_];
__device__ float g_Ctx[(size_t)M_*D_];      // [B*S][D] with D = h*64+hd

// ---------------------------------------------------------------------------
// Generic 128x128x8 SGEMM: C = A[M,K] @ W[K,N] + bias
// MODE 0: scatter output to heads layout [B,H,S,HD]
// MODE 1: plain row-major [M,N]
// ---------------------------------------------------------------------------
template<int MODE>
__global__ void __launch_bounds__(256, 2) sgemm128(
    const float* __restrict__ A,
    const float* __restrict__ W,
    const float* __restrict__ bias,
    float* __restrict__ C,
    int N, int K)
{
    __shared__ float As[8][128];   // transposed A tile: As[k][m]
    __shared__ float Bs[8][128];   // Bs[k][n]

    const int tid = threadIdx.x;
    const int m0 = blockIdx.y * 128;
    const int n0 = blockIdx.x * 128;
    const int ty = tid >> 4;       // 0..15
    const int tx = tid & 15;       // 0..15

    float acc[8][8];
#pragma unroll
    for (int i = 0; i < 8; i++)
#pragma unroll
        for (int j = 0; j < 8; j++) acc[i][j] = 0.0f;

    const int arow = tid >> 1;           // 0..127
    const int acol = (tid & 1) * 4;      // 0 or 4
    const int brow = tid >> 5;           // 0..7
    const int bcol = (tid & 31) * 4;     // 0..124

    const float* Ap = A + (size_t)(m0 + arow) * K + acol;
    const float* Bp = W + (size_t)brow * N + n0 + bcol;

    for (int k0 = 0; k0 < K; k0 += 8) {
        float4 av = *(const float4*)Ap; Ap += 8;
        float4 bv = *(const float4*)Bp; Bp += (size_t)8 * N;
        As[acol + 0][arow] = av.x;
        As[acol + 1][arow] = av.y;
        As[acol + 2][arow] = av.z;
        As[acol + 3][arow] = av.w;
        *(float4*)&Bs[brow][bcol] = bv;
        __syncthreads();
#pragma unroll
        for (int kk = 0; kk < 8; kk++) {
            float4 a0 = *(const float4*)&As[kk][ty * 4];
            float4 a1 = *(const float4*)&As[kk][64 + ty * 4];
            float4 b0 = *(const float4*)&Bs[kk][tx * 4];
            float4 b1 = *(const float4*)&Bs[kk][64 + tx * 4];
            float a[8] = {a0.x, a0.y, a0.z, a0.w, a1.x, a1.y, a1.z, a1.w};
            float b[8] = {b0.x, b0.y, b0.z, b0.w, b1.x, b1.y, b1.z, b1.w};
#pragma unroll
            for (int i = 0; i < 8; i++)
#pragma unroll
                for (int j = 0; j < 8; j++)
                    acc[i][j] += a[i] * b[j];
        }
        __syncthreads();
    }

    // Epilogue
#pragma unroll
    for (int ih = 0; ih < 2; ih++) {
#pragma unroll
        for (int i = 0; i < 4; i++) {
            int m = m0 + ih * 64 + ty * 4 + i;
            int bb = m >> 11;       // m / 2048
            int s  = m & 2047;
#pragma unroll
            for (int jh = 0; jh < 2; jh++) {
                int nb = n0 + jh * 64 + tx * 4;
                float4 bias4 = *(const float4*)&bias[nb];
                float4 v;
                v.x = acc[ih * 4 + i][jh * 4 + 0] + bias4.x;
                v.y = acc[ih * 4 + i][jh * 4 + 1] + bias4.y;
                v.z = acc[ih * 4 + i][jh * 4 + 2] + bias4.z;
                v.w = acc[ih * 4 + i][jh * 4 + 3] + bias4.w;
                if (MODE == 0) {
                    int h  = nb >> 6;
                    int hd = nb & 63;
                    size_t addr = (((size_t)bb * H_ + h) * S_ + s) * HD_ + hd;
                    *(float4*)&C[addr] = v;
                } else {
                    *(float4*)&C[(size_t)m * N + nb] = v;
                }
            }
        }
    }
}

// ---------------------------------------------------------------------------
// Attention: per CTA: one (b,h), 64 q rows, loop over 32 k-tiles of 64.
// softmax_1: attn = exp(s) / (1 + sum(exp(s)))   (raw exp, matches reference)
// ---------------------------------------------------------------------------
__global__ void __launch_bounds__(256) attn_kernel(
    const float* __restrict__ Q, const float* __restrict__ K,
    const float* __restrict__ V, float* __restrict__ Ctx)
{
    extern __shared__ float sm[];
    float* Qs   = sm;               // [d][q]  64*64
    float* Ks   = Qs + 64 * 64;     // [d][k]  64*66 (padded)
    float* Vs   = Ks + 64 * 66;     // [k][hd] 64*64
    float* Ps   = Vs + 64 * 64;     // [q][k]  64*64
    float* rs_s = Ps + 64 * 64;     // [64]

    const int tid = threadIdx.x;
    const int ty = tid >> 4;        // 0..15
    const int tx = tid & 15;        // 0..15
    const int bh = blockIdx.x;      // 0..63
    const int q0 = blockIdx.y * 64; // 0..2047

    const size_t base = (size_t)bh * S_ * HD_;
    const float* Qg = Q + base + (size_t)q0 * HD_;
    const float* Kg = K + base;
    const float* Vg = V + base;

    // Load Q tile transposed: Qs[d][q]
#pragma unroll
    for (int l = 0; l < 4; l++) {
        int fidx = tid + l * 256;        // float4 index 0..1023
        int r  = fidx >> 4;              // q row 0..63
        int c4 = fidx & 15;              // d/4
        float4 v = *(const float4*)(Qg + r * HD_ + c4 * 4);
        Qs[(c4 * 4 + 0) * 64 + r] = v.x;
        Qs[(c4 * 4 + 1) * 64 + r] = v.y;
        Qs[(c4 * 4 + 2) * 64 + r] = v.z;
        Qs[(c4 * 4 + 3) * 64 + r] = v.w;
    }

    float o[4][4];
#pragma unroll
    for (int i = 0; i < 4; i++)
#pragma unroll
        for (int j = 0; j < 4; j++) o[i][j] = 0.0f;
    float rs[4] = {0.f, 0.f, 0.f, 0.f};

    for (int kt = 0; kt < S_ / 64; kt++) {
        __syncthreads();   // prev iteration done reading Ks/Vs/Ps
        // Load K transposed [d][k] (pad 66) and V natural [k][hd]
#pragma unroll
        for (int l = 0; l < 4; l++) {
            int fidx = tid + l * 256;
            int r  = fidx >> 4;
            int c4 = fidx & 15;
            float4 kv = *(const float4*)(Kg + (size_t)(kt * 64 + r) * HD_ + c4 * 4);
            Ks[(c4 * 4 + 0) * 66 + r] = kv.x;
            Ks[(c4 * 4 + 1) * 66 + r] = kv.y;
            Ks[(c4 * 4 + 2) * 66 + r] = kv.z;
            Ks[(c4 * 4 + 3) * 66 + r] = kv.w;
            float4 vv = *(const float4*)(Vg + (size_t)(kt * 64 + r) * HD_ + c4 * 4);
            *(float4*)&Vs[r * 64 + c4 * 4] = vv;
        }
        __syncthreads();

        // P[q][k] = Q . K  (outer product over d)
        float p[4][4];
#pragma unroll
        for (int i = 0; i < 4; i++)
#pragma unroll
            for (int j = 0; j < 4; j++) p[i][j] = 0.0f;
#pragma unroll 16
        for (int d = 0; d < 64; d++) {
            float4 qv  = *(const float4*)&Qs[d * 64 + ty * 4];
            float2 k01 = *(const float2*)&Ks[d * 66 + tx * 4];
            float2 k23 = *(const float2*)&Ks[d * 66 + tx * 4 + 2];
            float qa[4] = {qv.x, qv.y, qv.z, qv.w};
            float ka[4] = {k01.x, k01.y, k23.x, k23.y};
#pragma unroll
            for (int i = 0; i < 4; i++)
#pragma unroll
                for (int j = 0; j < 4; j++)
                    p[i][j] += qa[i] * ka[j];
        }

        // exp, rowsum (shfl over the 16 tx lanes), store P
#pragma unroll
        for (int i = 0; i < 4; i++) {
            float e0 = __expf(p[i][0] * 0.125f);
            float e1 = __expf(p[i][1] * 0.125f);
            float e2 = __expf(p[i][2] * 0.125f);
            float e3 = __expf(p[i][3] * 0.125f);
            float sum = e0 + e1 + e2 + e3;
            sum += __shfl_xor_sync(0xffffffffu, sum, 1);
            sum += __shfl_xor_sync(0xffffffffu, sum, 2);
            sum += __shfl_xor_sync(0xffffffffu, sum, 4);
            sum += __shfl_xor_sync(0xffffffffu, sum, 8);
            rs[i] += sum;
            float4 ev = {e0, e1, e2, e3};
            *(float4*)&Ps[(ty * 4 + i) * 64 + tx * 4] = ev;
        }
        __syncthreads();

        // O += P @ V
#pragma unroll 4
        for (int k4 = 0; k4 < 16; k4++) {
            float4 pv[4], vv[4];
#pragma unroll
            for (int i = 0; i < 4; i++)
                pv[i] = *(const float4*)&Ps[(ty * 4 + i) * 64 + k4 * 4];
#pragma unroll
            for (int c = 0; c < 4; c++)
                vv[c] = *(const float4*)&Vs[(k4 * 4 + c) * 64 + tx * 4];
#pragma unroll
            for (int i = 0; i < 4; i++) {
                o[i][0] += pv[i].x * vv[0].x + pv[i].y * vv[1].x + pv[i].z * vv[2].x + pv[i].w * vv[3].x;
                o[i][1] += pv[i].x * vv[0].y + pv[i].y * vv[1].y + pv[i].z * vv[2].y + pv[i].w * vv[3].y;
                o[i][2] += pv[i].x * vv[0].z + pv[i].y * vv[1].z + pv[i].z * vv[2].z + pv[i].w * vv[3].z;
                o[i][3] += pv[i].x * vv[0].w + pv[i].y * vv[1].w + pv[i].z * vv[2].w + pv[i].w * vv[3].w;
            }
        }
    }

    // finalize: divide by (1 + rowsum), write ctx in [B,S,D] (D = h*64+hd)
    if (tx == 0) {
#pragma unroll
        for (int i = 0; i < 4; i++) rs_s[ty * 4 + i] = rs[i];
    }
    __syncthreads();

    const int bb = bh >> 4;
    const int h  = bh & 15;
#pragma unroll
    for (int i = 0; i < 4; i++) {
        int q = ty * 4 + i;
        float inv = 1.0f / (1.0f + rs_s[q]);
        float4 v;
        v.x = o[i][0] * inv;
        v.y = o[i][1] * inv;
        v.z = o[i][2] * inv;
        v.w = o[i][3] * inv;
        size_t addr = ((size_t)bb * S_ + q0 + q) * D_ + h * HD_ + tx * 4;
        *(float4*)&Ctx[addr] = v;
    }
}

// ---------------------------------------------------------------------------
extern "C" void kernel_launch(void* const* d_in, const int* in_sizes, int n_in,
                              void* d_out, int out_size)
{
    (void)in_sizes; (void)n_in; (void)out_size;
    const float* query = (const float*)d_in[0];
    const float* key   = (const float*)d_in[1];
    const float* value = (const float*)d_in[2];
    const float* Wq = (const float*)d_in[3];
    const float* bq = (const float*)d_in[4];
    const float* Wk = (const float*)d_in[5];
    const float* bk = (const float*)d_in[6];
    const float* Wv = (const float*)d_in[7];
    const float* bv = (const float*)d_in[8];
    const float* Wf = (const float*)d_in[9];
    const float* bf = (const float*)d_in[10];

    float *Qp, *Kp, *Vp, *Cp;
    cudaGetSymbolAddress((void**)&Qp, g_Q);
    cudaGetSymbolAddress((void**)&Kp, g_K);
    cudaGetSymbolAddress((void**)&Vp, g_V);
    cudaGetSymbolAddress((void**)&Cp, g_Ctx);

    dim3 gProj(D_ / 128, M_ / 128);  // (8, 64)
    sgemm128<0><<<gProj, 256>>>(query, Wq, bq, Qp, D_, D_);
    sgemm128<0><<<gProj, 256>>>(key,   Wk, bk, Kp, D_, D_);
    sgemm128<0><<<gProj, 256>>>(value, Wv, bv, Vp, D_, D_);

    int smem = (64*64 + 64*66 + 64*64 + 64*64 + 64) * (int)sizeof(float);  // 66560 B
    cudaFuncSetAttribute(attn_kernel, cudaFuncAttributeMaxDynamicSharedMemorySize, smem);
    attn_kernel<<<dim3(BH_, S_ / 64), 256, smem>>>(Qp, Kp, Vp, Cp);

    dim3 gOut(OUT_ / 128, M_ / 128); // (2, 64)
    sgemm128<1><<<gOut, 256>>>(Cp, Wf, bf, (float*)d_out, OUT_, D_);
}

// round 5
// speedup vs baseline: 3.1372x; 3.1372x over previous
#include <cuda_runtime.h>
#include <cuda_bf16.h>
#include <cstdint>

#define B_ 4
#define S_ 2048
#define D_ 1024
#define H_ 16
#define HD_ 64
#define OUT_ 256
#define M_ (B_*S_)
#define BH_ (B_*H_)

static constexpr size_t SZX = (size_t)M_ * D_;
static constexpr size_t SZW = (size_t)D_ * D_;
static constexpr size_t SZF = (size_t)D_ * OUT_;

static constexpr size_t O_XQH = 0,            O_XQL = O_XQH + SZX;
static constexpr size_t O_XKH = O_XQL + SZX,  O_XKL = O_XKH + SZX;
static constexpr size_t O_XVH = O_XKL + SZX,  O_XVL = O_XVH + SZX;
static constexpr size_t O_WQH = O_XVL + SZX,  O_WQL = O_WQH + SZW;
static constexpr size_t O_WKH = O_WQL + SZW,  O_WKL = O_WKH + SZW;
static constexpr size_t O_WVH = O_WKL + SZW,  O_WVL = O_WVH + SZW;
static constexpr size_t O_WFH = O_WVL + SZW,  O_WFL = O_WFH + SZF;
static constexpr size_t O_QH  = O_WFL + SZF,  O_QL  = O_QH + SZX;
static constexpr size_t O_KH  = O_QL + SZX,   O_KL  = O_KH + SZX;
static constexpr size_t O_VTH = O_KL + SZX,   O_VTL = O_VTH + SZX;
static constexpr size_t O_CH  = O_VTL + SZX,  O_CL  = O_CH + SZX;
static constexpr size_t TOTAL_BF = O_CL + SZX;

__device__ __nv_bfloat16 g_bf[TOTAL_BF];

// ---------------- helpers ----------------
__device__ __forceinline__ uint32_t smem_u32(const void* p) {
    uint32_t a;
    asm("{ .reg .u64 t; cvta.to.shared.u64 t, %1; cvt.u32.u64 %0, t; }" : "=r"(a) : "l"(p));
    return a;
}
__device__ __forceinline__ void ldsm4(uint32_t* r, uint32_t a) {
    asm volatile("ldmatrix.sync.aligned.m8n8.x4.shared.b16 {%0,%1,%2,%3}, [%4];"
        : "=r"(r[0]), "=r"(r[1]), "=r"(r[2]), "=r"(r[3]) : "r"(a));
}
__device__ __forceinline__ void mma_bf16(float* d, const uint32_t* a, const uint32_t* b) {
    asm volatile("mma.sync.aligned.m16n8k16.row.col.f32.bf16.bf16.f32 "
        "{%0,%1,%2,%3}, {%4,%5,%6,%7}, {%8,%9}, {%0,%1,%2,%3};"
        : "+f"(d[0]), "+f"(d[1]), "+f"(d[2]), "+f"(d[3])
        : "r"(a[0]), "r"(a[1]), "r"(a[2]), "r"(a[3]), "r"(b[0]), "r"(b[1]));
}
__device__ __forceinline__ void cpa16(uint32_t dst, const void* src) {
    asm volatile("cp.async.cg.shared.global [%0], [%1], 16;" :: "r"(dst), "l"(src));
}
#define CP_COMMIT() asm volatile("cp.async.commit_group;" ::: "memory")
#define CP_WAIT(n)  asm volatile("cp.async.wait_group %0;" :: "n"(n) : "memory")

__device__ __forceinline__ uint32_t swz128(uint32_t o) { return o ^ ((o >> 3) & 0x70); }
__device__ __forceinline__ uint32_t swz256(uint32_t o) { return o ^ ((o >> 4) & 0x70); }
__device__ __forceinline__ uint32_t pack2(float a, float b) {
    __nv_bfloat162 t = __floats2bfloat162_rn(a, b);
    return *(uint32_t*)&t;
}
__device__ __forceinline__ float bfh(float v) {
    return __bfloat162float(__float2bfloat16(v));
}

// ---------------- conversions ----------------
__global__ void split_f32(const float* __restrict__ x,
                          __nv_bfloat16* __restrict__ hi,
                          __nv_bfloat16* __restrict__ lo, int n4) {
    int i = blockIdx.x * blockDim.x + threadIdx.x;
    if (i >= n4) return;
    float4 v = ((const float4*)x)[i];
    float a[4] = {v.x, v.y, v.z, v.w};
    float h[4];
#pragma unroll
    for (int j = 0; j < 4; j++) h[j] = bfh(a[j]);
    ((uint32_t*)hi)[i*2]   = pack2(h[0], h[1]);
    ((uint32_t*)hi)[i*2+1] = pack2(h[2], h[3]);
    ((uint32_t*)lo)[i*2]   = pack2(a[0]-h[0], a[1]-h[1]);
    ((uint32_t*)lo)[i*2+1] = pack2(a[2]-h[2], a[3]-h[3]);
}

__global__ void transpose_split(const float* __restrict__ W,
                                __nv_bfloat16* __restrict__ Th,
                                __nv_bfloat16* __restrict__ Tl,
                                int Kdim, int Ndim) {
    __shared__ float t[32][33];
    const int n0 = blockIdx.x * 32, k0 = blockIdx.y * 32;
    const int tx = threadIdx.x & 31, ty = threadIdx.x >> 5;
#pragma unroll
    for (int i = 0; i < 32; i += 8)
        t[ty + i][tx] = W[(size_t)(k0 + ty + i) * Ndim + n0 + tx];
    __syncthreads();
#pragma unroll
    for (int i = 0; i < 32; i += 8) {
        float v = t[tx][ty + i];
        float h = bfh(v);
        size_t o = (size_t)(n0 + ty + i) * Kdim + k0 + tx;
        Th[o] = __float2bfloat16(h);
        Tl[o] = __float2bfloat16(v - h);
    }
}

// ---------------- mma.sync split GEMM ----------------
// C[128,128] = A[128,1024] @ B[n][k]^T via 3-phase split (K_eff = 3072)
// EPI 0: heads bf16 planes +bias; EPI 1: fp32 row-major +bias; EPI 2: V^T planes +bias
template<int EPI>
__global__ void __launch_bounds__(256) gemm_mma(
    const __nv_bfloat16* __restrict__ Ah, const __nv_bfloat16* __restrict__ Al,
    const __nv_bfloat16* __restrict__ Bh, const __nv_bfloat16* __restrict__ Bl,
    const float* __restrict__ bias,
    __nv_bfloat16* __restrict__ Oh, __nv_bfloat16* __restrict__ Ol,
    float* __restrict__ Of, int Nout)
{
    extern __shared__ __align__(1024) char sm[];
    const uint32_t sb = smem_u32(sm);
    const int tid = threadIdx.x, wid = tid >> 5, lane = tid & 31;
    const int m0 = blockIdx.y * 128, n0 = blockIdx.x * 128;
    const int wr = wid >> 1, wc = wid & 1;

    float acc[2][8][4];
#pragma unroll
    for (int i = 0; i < 2; i++)
#pragma unroll
        for (int j = 0; j < 8; j++)
#pragma unroll
            for (int q = 0; q < 4; q++) acc[i][j][q] = 0.0f;

    auto issue = [&](int c) {
        const int ph = c >> 4, kk = (c & 15) * 64;
        const __nv_bfloat16* Ap = (ph < 2) ? Ah : Al;
        const __nv_bfloat16* Bp = (ph == 1) ? Bl : Bh;
        const uint32_t dA = sb + (uint32_t)(c & 1) * 32768u;
        const uint32_t dB = dA + 16384u;
#pragma unroll
        for (int i = 0; i < 4; i++) {
            int fidx = tid + i * 256;
            int row = fidx >> 3, cc = fidx & 7;
            uint32_t off = swz128((uint32_t)(row * 128 + cc * 16));
            cpa16(dA + off, Ap + (size_t)(m0 + row) * 1024 + kk + cc * 8);
            cpa16(dB + off, Bp + (size_t)(n0 + row) * 1024 + kk + cc * 8);
        }
        CP_COMMIT();
    };

    issue(0);
    for (int c = 0; c < 48; c++) {
        if (c + 1 < 48) { issue(c + 1); CP_WAIT(1); }
        else            { CP_WAIT(0); }
        __syncthreads();
        const uint32_t sA = sb + (uint32_t)(c & 1) * 32768u;
        const uint32_t sB = sA + 16384u;
#pragma unroll
        for (int s = 0; s < 4; s++) {
            uint32_t aF[2][4], bF[4][4];
            {
                const int row16 = (lane & 7) | (((lane >> 3) & 1) << 3);
                const int colb = ((lane >> 4) << 4) + s * 32;
#pragma unroll
                for (int mt = 0; mt < 2; mt++)
                    ldsm4(aF[mt], sA + swz128((uint32_t)(((wr * 32 + mt * 16 + row16) << 7) + colb)));
            }
            {
                const int row16 = (lane & 7) | ((lane >> 4) << 3);
                const int colb = (((lane >> 3) & 1) << 4) + s * 32;
#pragma unroll
                for (int p = 0; p < 4; p++)
                    ldsm4(bF[p], sB + swz128((uint32_t)(((wc * 64 + p * 16 + row16) << 7) + colb)));
            }
#pragma unroll
            for (int mt = 0; mt < 2; mt++)
#pragma unroll
                for (int nt = 0; nt < 8; nt++)
                    mma_bf16(acc[mt][nt], aF[mt], &bF[nt >> 1][(nt & 1) * 2]);
        }
        __syncthreads();
    }

    // epilogue
#pragma unroll
    for (int mt = 0; mt < 2; mt++) {
        const int r0 = m0 + wr * 32 + mt * 16 + (lane >> 2);
#pragma unroll
        for (int half = 0; half < 2; half++) {
            const int m = r0 + half * 8;
            const int b = m >> 11, s = m & 2047;
#pragma unroll
            for (int nt = 0; nt < 8; nt++) {
                const int n = n0 + wc * 64 + nt * 8 + (lane & 3) * 2;
                float v0 = acc[mt][nt][half * 2]     + __ldg(&bias[n]);
                float v1 = acc[mt][nt][half * 2 + 1] + __ldg(&bias[n + 1]);
                if (EPI == 1) {
                    float2 o = {v0, v1};
                    *(float2*)&Of[(size_t)m * Nout + n] = o;
                } else if (EPI == 0) {
                    const int h = n >> 6, hd = n & 63;
                    float h0 = bfh(v0), h1 = bfh(v1);
                    size_t addr = (((size_t)b * H_ + h) * S_ + s) * HD_ + hd;
                    *(uint32_t*)&Oh[addr] = pack2(h0, h1);
                    *(uint32_t*)&Ol[addr] = pack2(v0 - h0, v1 - h1);
                } else {
                    const int h = n >> 6, hd = n & 63;
                    float h0 = bfh(v0), h1 = bfh(v1);
                    size_t a0 = (((size_t)b * H_ + h) * HD_ + hd) * S_ + s;
                    size_t a1 = (((size_t)b * H_ + h) * HD_ + hd + 1) * S_ + s;
                    Oh[a0] = __float2bfloat16(h0);      Ol[a0] = __float2bfloat16(v0 - h0);
                    Oh[a1] = __float2bfloat16(h1);      Ol[a1] = __float2bfloat16(v1 - h1);
                }
            }
        }
    }
}

// ---------------- attention (mma.sync, FA2 layout) ----------------
// CTA: 128 q rows x one (b,h). 8 warps x 16 q rows, full 128-kv width.
__global__ void __launch_bounds__(256) attn_mma(
    const __nv_bfloat16* __restrict__ QH, const __nv_bfloat16* __restrict__ QL,
    const __nv_bfloat16* __restrict__ KH, const __nv_bfloat16* __restrict__ KL,
    const __nv_bfloat16* __restrict__ VTH, const __nv_bfloat16* __restrict__ VTL,
    __nv_bfloat16* __restrict__ CH, __nv_bfloat16* __restrict__ CL)
{
    extern __shared__ __align__(1024) char sm[];
    const uint32_t sb = smem_u32(sm);
    // layout: Qh 0 (16K), Ql 16384; stages at 32768 + st*65536:
    //   Kh +0, Kl +16384, Vh +32768, Vl +49152
    const int tid = threadIdx.x, wid = tid >> 5, lane = tid & 31;
    const int bh = blockIdx.x, q0 = blockIdx.y * 128;
    const size_t baseQ = (size_t)bh * S_ * HD_ + (size_t)q0 * HD_;
    const size_t baseK = (size_t)bh * S_ * HD_;
    const size_t baseV = (size_t)bh * HD_ * S_;

    auto issueKV = [&](int t) {
        const uint32_t st = sb + 32768u + (uint32_t)(t & 1) * 65536u;
#pragma unroll
        for (int i = 0; i < 4; i++) {
            int fidx = tid + i * 256;
            int kr = fidx >> 3, kc = fidx & 7;
            uint32_t ko = swz128((uint32_t)(kr * 128 + kc * 16));
            const size_t ks = baseK + (size_t)(t * 128 + kr) * 64 + kc * 8;
            cpa16(st + ko,          KH + ks);
            cpa16(st + 16384u + ko, KL + ks);
            int vr = fidx >> 4, vc = fidx & 15;
            uint32_t vo = swz256((uint32_t)(vr * 256 + vc * 16));
            const size_t vs = baseV + (size_t)vr * S_ + t * 128 + vc * 8;
            cpa16(st + 32768u + vo, VTH + vs);
            cpa16(st + 49152u + vo, VTL + vs);
        }
        CP_COMMIT();
    };

    // prologue: Q tiles + stage 0
#pragma unroll
    for (int i = 0; i < 4; i++) {
        int fidx = tid + i * 256;
        int row = fidx >> 3, cc = fidx & 7;
        uint32_t off = swz128((uint32_t)(row * 128 + cc * 16));
        cpa16(sb + off,          QH + baseQ + (size_t)row * 64 + cc * 8);
        cpa16(sb + 16384u + off, QL + baseQ + (size_t)row * 64 + cc * 8);
    }
    CP_COMMIT();
    issueKV(0);
    CP_WAIT(1);
    __syncthreads();

    // Q fragments (A-operand), per warp rows wid*16..+15
    uint32_t qh[4][4], ql[4][4];
    {
        const int row16 = (lane & 7) | (((lane >> 3) & 1) << 3);
#pragma unroll
        for (int ds = 0; ds < 4; ds++) {
            const int colb = ((lane >> 4) << 4) + ds * 32;
            uint32_t off = swz128((uint32_t)(((wid * 16 + row16) << 7) + colb));
            ldsm4(qh[ds], sb + off);
            ldsm4(ql[ds], sb + 16384u + off);
        }
    }

    float accO[8][4];
#pragma unroll
    for (int i = 0; i < 8; i++)
#pragma unroll
        for (int j = 0; j < 4; j++) accO[i][j] = 0.0f;
    float rs0 = 0.0f, rs1 = 0.0f;

    const int rowB = (lane & 7) | ((lane >> 4) << 3);   // B-operand ldsm row
    const int colBh = ((lane >> 3) & 1) << 4;

    for (int t = 0; t < 16; t++) {
        if (t + 1 < 16) { issueKV(t + 1); CP_WAIT(1); }
        else            { CP_WAIT(0); }
        __syncthreads();
        const uint32_t st = sb + 32768u + (uint32_t)(t & 1) * 65536u;

        // S = Qh*Kh + Ql*Kh + Qh*Kl   (scaled later)
        float accS[16][4];
#pragma unroll
        for (int i = 0; i < 16; i++)
#pragma unroll
            for (int j = 0; j < 4; j++) accS[i][j] = 0.0f;

#pragma unroll
        for (int ds = 0; ds < 4; ds++) {
            const int colb = colBh + ds * 32;
#pragma unroll
            for (int p = 0; p < 8; p++) {
                uint32_t bh_[4], bl_[4];
                uint32_t off = swz128((uint32_t)(((p * 16 + rowB) << 7) + colb));
                ldsm4(bh_, st + off);
                ldsm4(bl_, st + 16384u + off);
#pragma unroll
                for (int half = 0; half < 2; half++) {
                    const int nt = p * 2 + half;
                    mma_bf16(accS[nt], qh[ds], &bh_[half * 2]);
                    mma_bf16(accS[nt], ql[ds], &bh_[half * 2]);
                    mma_bf16(accS[nt], qh[ds], &bl_[half * 2]);
                }
            }
        }

        // exp + rowsum
#pragma unroll
        for (int nt = 0; nt < 16; nt++) {
            float e0 = __expf(accS[nt][0] * 0.125f);
            float e1 = __expf(accS[nt][1] * 0.125f);
            float e2 = __expf(accS[nt][2] * 0.125f);
            float e3 = __expf(accS[nt][3] * 0.125f);
            rs0 += e0 + e1; rs1 += e2 + e3;
            accS[nt][0] = e0; accS[nt][1] = e1; accS[nt][2] = e2; accS[nt][3] = e3;
        }

        // O += Ph*Vh + Ph*Vl + Pl*Vh
#pragma unroll
        for (int j = 0; j < 8; j++) {
            uint32_t ah[4], al[4];
            {
                const float* c0 = accS[2 * j];
                const float* c1 = accS[2 * j + 1];
                float h00 = bfh(c0[0]), h01 = bfh(c0[1]), h02 = bfh(c0[2]), h03 = bfh(c0[3]);
                float h10 = bfh(c1[0]), h11 = bfh(c1[1]), h12 = bfh(c1[2]), h13 = bfh(c1[3]);
                ah[0] = pack2(h00, h01); ah[1] = pack2(h02, h03);
                ah[2] = pack2(h10, h11); ah[3] = pack2(h12, h13);
                al[0] = pack2(c0[0] - h00, c0[1] - h01); al[1] = pack2(c0[2] - h02, c0[3] - h03);
                al[2] = pack2(c1[0] - h10, c1[1] - h11); al[3] = pack2(c1[2] - h12, c1[3] - h13);
            }
            const int colb = colBh + j * 32;
#pragma unroll
            for (int p = 0; p < 4; p++) {
                uint32_t vh_[4], vl_[4];
                uint32_t off = swz256((uint32_t)(((p * 16 + rowB) << 8) + colb));
                ldsm4(vh_, st + 32768u + off);
                ldsm4(vl_, st + 49152u + off);
#pragma unroll
                for (int half = 0; half < 2; half++) {
                    const int nt = p * 2 + half;
                    mma_bf16(accO[nt], ah, &vh_[half * 2]);
                    mma_bf16(accO[nt], al, &vh_[half * 2]);
                    mma_bf16(accO[nt], ah, &vl_[half * 2]);
                }
            }
        }
        __syncthreads();
    }

    // finalize
    rs0 += __shfl_xor_sync(0xffffffffu, rs0, 1);
    rs0 += __shfl_xor_sync(0xffffffffu, rs0, 2);
    rs1 += __shfl_xor_sync(0xffffffffu, rs1, 1);
    rs1 += __shfl_xor_sync(0xffffffffu, rs1, 2);
    const float inv0 = 1.0f / (1.0f + rs0);
    const float inv1 = 1.0f / (1.0f + rs1);

    const int b = bh >> 4, h = bh & 15;
    const int qA = q0 + wid * 16 + (lane >> 2);
#pragma unroll
    for (int half = 0; half < 2; half++) {
        const int q = qA + half * 8;
        const float inv = half ? inv1 : inv0;
        const size_t rowb = ((size_t)b * S_ + q) * D_ + h * HD_;
#pragma unroll
        for (int nt = 0; nt < 8; nt++) {
            const int col = nt * 8 + (lane & 3) * 2;
            float v0 = accO[nt][half * 2]     * inv;
            float v1 = accO[nt][half * 2 + 1] * inv;
            float h0 = bfh(v0), h1 = bfh(v1);
            *(uint32_t*)&CH[rowb + col] = pack2(h0, h1);
            *(uint32_t*)&CL[rowb + col] = pack2(v0 - h0, v1 - h1);
        }
    }
}

// ---------------- host ----------------
extern "C" void kernel_launch(void* const* d_in, const int* in_sizes, int n_in,
                              void* d_out, int out_size)
{
    (void)in_sizes; (void)n_in; (void)out_size;
    const float* query = (const float*)d_in[0];
    const float* key   = (const float*)d_in[1];
    const float* value = (const float*)d_in[2];
    const float* Wq = (const float*)d_in[3];
    const float* bq = (const float*)d_in[4];
    const float* Wk = (const float*)d_in[5];
    const float* bk = (const float*)d_in[6];
    const float* Wv = (const float*)d_in[7];
    const float* bv = (const float*)d_in[8];
    const float* Wf = (const float*)d_in[9];
    const float* bf = (const float*)d_in[10];

    __nv_bfloat16* G;
    cudaGetSymbolAddress((void**)&G, g_bf);

    const int n4 = (int)(SZX / 4);
    split_f32<<<n4 / 256, 256>>>(query, G + O_XQH, G + O_XQL, n4);
    split_f32<<<n4 / 256, 256>>>(key,   G + O_XKH, G + O_XKL, n4);
    split_f32<<<n4 / 256, 256>>>(value, G + O_XVH, G + O_XVL, n4);

    transpose_split<<<dim3(32, 32), 256>>>(Wq, G + O_WQH, G + O_WQL, D_, D_);
    transpose_split<<<dim3(32, 32), 256>>>(Wk, G + O_WKH, G + O_WKL, D_, D_);
    transpose_split<<<dim3(32, 32), 256>>>(Wv, G + O_WVH, G + O_WVL, D_, D_);
    transpose_split<<<dim3(8, 32),  256>>>(Wf, G + O_WFH, G + O_WFL, D_, OUT_);

    const int gsm = 65536;
    cudaFuncSetAttribute(gemm_mma<0>, cudaFuncAttributeMaxDynamicSharedMemorySize, gsm);
    cudaFuncSetAttribute(gemm_mma<1>, cudaFuncAttributeMaxDynamicSharedMemorySize, gsm);
    cudaFuncSetAttribute(gemm_mma<2>, cudaFuncAttributeMaxDynamicSharedMemorySize, gsm);

    dim3 gP(D_ / 128, M_ / 128);  // (8, 64)
    gemm_mma<0><<<gP, 256, gsm>>>(G + O_XQH, G + O_XQL, G + O_WQH, G + O_WQL, bq,
                                  G + O_QH, G + O_QL, nullptr, D_);
    gemm_mma<0><<<gP, 256, gsm>>>(G + O_XKH, G + O_XKL, G + O_WKH, G + O_WKL, bk,
                                  G + O_KH, G + O_KL, nullptr, D_);
    gemm_mma<2><<<gP, 256, gsm>>>(G + O_XVH, G + O_XVL, G + O_WVH, G + O_WVL, bv,
                                  G + O_VTH, G + O_VTL, nullptr, D_);

    const int asm_ = 32768 + 2 * 65536;  // 163840
    cudaFuncSetAttribute(attn_mma, cudaFuncAttributeMaxDynamicSharedMemorySize, asm_);
    attn_mma<<<dim3(BH_, S_ / 128), 256, asm_>>>(
        G + O_QH, G + O_QL, G + O_KH, G + O_KL, G + O_VTH, G + O_VTL,
        G + O_CH, G + O_CL);

    dim3 gF(OUT_ / 128, M_ / 128);  // (2, 64)
    gemm_mma<1><<<gF, 256, gsm>>>(G + O_CH, G + O_CL, G + O_WFH, G + O_WFL, bf,
                                  nullptr, nullptr, (float*)d_out, OUT_);
}

// round 6
// speedup vs baseline: 3.3505x; 1.0680x over previous
#include <cuda_runtime.h>
#include <cuda_bf16.h>
#include <cstdint>

#define B_ 4
#define S_ 2048
#define D_ 1024
#define H_ 16
#define HD_ 64
#define OUT_ 256
#define M_ (B_*S_)
#define BH_ (B_*H_)

static constexpr size_t SZX = (size_t)M_ * D_;
static constexpr size_t SZW = (size_t)D_ * D_;
static constexpr size_t SZF = (size_t)D_ * OUT_;

static constexpr size_t O_XQH = 0,            O_XQL = O_XQH + SZX;
static constexpr size_t O_XKH = O_XQL + SZX,  O_XKL = O_XKH + SZX;
static constexpr size_t O_XVH = O_XKL + SZX,  O_XVL = O_XVH + SZX;
static constexpr size_t O_WQH = O_XVL + SZX,  O_WQL = O_WQH + SZW;
static constexpr size_t O_WKH = O_WQL + SZW,  O_WKL = O_WKH + SZW;
static constexpr size_t O_WVH = O_WKL + SZW,  O_WVL = O_WVH + SZW;
static constexpr size_t O_WFH = O_WVL + SZW,  O_WFL = O_WFH + SZF;
static constexpr size_t O_QH  = O_WFL + SZF,  O_QL  = O_QH + SZX;
static constexpr size_t O_KH  = O_QL + SZX,   O_KL  = O_KH + SZX;
static constexpr size_t O_VH  = O_KL + SZX,   O_VL  = O_VH + SZX;
static constexpr size_t O_CH  = O_VL + SZX,   O_CL  = O_CH + SZX;
static constexpr size_t TOTAL_BF = O_CL + SZX;

__device__ __nv_bfloat16 g_bf[TOTAL_BF];

// ---------------- helpers ----------------
__device__ __forceinline__ uint32_t smem_u32(const void* p) {
    uint32_t a;
    asm("{ .reg .u64 t; cvta.to.shared.u64 t, %1; cvt.u32.u64 %0, t; }" : "=r"(a) : "l"(p));
    return a;
}
__device__ __forceinline__ void ldsm4(uint32_t* r, uint32_t a) {
    asm volatile("ldmatrix.sync.aligned.m8n8.x4.shared.b16 {%0,%1,%2,%3}, [%4];"
        : "=r"(r[0]), "=r"(r[1]), "=r"(r[2]), "=r"(r[3]) : "r"(a));
}
__device__ __forceinline__ void ldsm4t(uint32_t* r, uint32_t a) {
    asm volatile("ldmatrix.sync.aligned.m8n8.x4.trans.shared.b16 {%0,%1,%2,%3}, [%4];"
        : "=r"(r[0]), "=r"(r[1]), "=r"(r[2]), "=r"(r[3]) : "r"(a));
}
__device__ __forceinline__ void mma_bf16(float* d, const uint32_t* a, const uint32_t* b) {
    asm volatile("mma.sync.aligned.m16n8k16.row.col.f32.bf16.bf16.f32 "
        "{%0,%1,%2,%3}, {%4,%5,%6,%7}, {%8,%9}, {%0,%1,%2,%3};"
        : "+f"(d[0]), "+f"(d[1]), "+f"(d[2]), "+f"(d[3])
        : "r"(a[0]), "r"(a[1]), "r"(a[2]), "r"(a[3]), "r"(b[0]), "r"(b[1]));
}
__device__ __forceinline__ void cpa16(uint32_t dst, const void* src) {
    asm volatile("cp.async.cg.shared.global [%0], [%1], 16;" :: "r"(dst), "l"(src));
}
#define CP_COMMIT() asm volatile("cp.async.commit_group;" ::: "memory")
#define CP_WAIT(n)  asm volatile("cp.async.wait_group %0;" :: "n"(n) : "memory")

__device__ __forceinline__ uint32_t swz128(uint32_t o) { return o ^ ((o >> 3) & 0x70); }
__device__ __forceinline__ uint32_t pack2(float a, float b) {
    __nv_bfloat162 t = __floats2bfloat162_rn(a, b);
    return *(uint32_t*)&t;
}
__device__ __forceinline__ float bfh(float v) {
    return __bfloat162float(__float2bfloat16(v));
}

// ---------------- conversions ----------------
__global__ void split_f32(const float* __restrict__ x,
                          __nv_bfloat16* __restrict__ hi,
                          __nv_bfloat16* __restrict__ lo, int n4) {
    int i = blockIdx.x * blockDim.x + threadIdx.x;
    if (i >= n4) return;
    float4 v = ((const float4*)x)[i];
    float a[4] = {v.x, v.y, v.z, v.w};
    float h[4];
#pragma unroll
    for (int j = 0; j < 4; j++) h[j] = bfh(a[j]);
    ((uint32_t*)hi)[i*2]   = pack2(h[0], h[1]);
    ((uint32_t*)hi)[i*2+1] = pack2(h[2], h[3]);
    ((uint32_t*)lo)[i*2]   = pack2(a[0]-h[0], a[1]-h[1]);
    ((uint32_t*)lo)[i*2+1] = pack2(a[2]-h[2], a[3]-h[3]);
}

__global__ void transpose_split(const float* __restrict__ W,
                                __nv_bfloat16* __restrict__ Th,
                                __nv_bfloat16* __restrict__ Tl,
                                int Kdim, int Ndim) {
    __shared__ float t[32][33];
    const int n0 = blockIdx.x * 32, k0 = blockIdx.y * 32;
    const int tx = threadIdx.x & 31, ty = threadIdx.x >> 5;
#pragma unroll
    for (int i = 0; i < 32; i += 8)
        t[ty + i][tx] = W[(size_t)(k0 + ty + i) * Ndim + n0 + tx];
    __syncthreads();
#pragma unroll
    for (int i = 0; i < 32; i += 8) {
        float v = t[tx][ty + i];
        float h = bfh(v);
        size_t o = (size_t)(n0 + ty + i) * Kdim + k0 + tx;
        Th[o] = __float2bfloat16(h);
        Tl[o] = __float2bfloat16(v - h);
    }
}

// ---------------- mma.sync split GEMM ----------------
// C[128,128] = A[128,1024] @ B[n][k]^T via 3-phase split (K_eff = 3072)
// EPI 0: heads bf16 planes +bias; EPI 1: fp32 row-major +bias
template<int EPI>
__global__ void __launch_bounds__(256, 2) gemm_mma(
    const __nv_bfloat16* __restrict__ Ah, const __nv_bfloat16* __restrict__ Al,
    const __nv_bfloat16* __restrict__ Bh, const __nv_bfloat16* __restrict__ Bl,
    const float* __restrict__ bias,
    __nv_bfloat16* __restrict__ Oh, __nv_bfloat16* __restrict__ Ol,
    float* __restrict__ Of, int Nout)
{
    extern __shared__ __align__(1024) char sm[];
    const uint32_t sb = smem_u32(sm);
    const int tid = threadIdx.x, wid = tid >> 5, lane = tid & 31;
    const int m0 = blockIdx.y * 128, n0 = blockIdx.x * 128;
    const int wr = wid >> 1, wc = wid & 1;

    float acc[2][8][4];
#pragma unroll
    for (int i = 0; i < 2; i++)
#pragma unroll
        for (int j = 0; j < 8; j++)
#pragma unroll
            for (int q = 0; q < 4; q++) acc[i][j][q] = 0.0f;

    auto issue = [&](int c) {
        const int ph = c >> 4, kk = (c & 15) * 64;
        const __nv_bfloat16* Ap = (ph < 2) ? Ah : Al;
        const __nv_bfloat16* Bp = (ph == 1) ? Bl : Bh;
        const uint32_t dA = sb + (uint32_t)(c & 1) * 32768u;
        const uint32_t dB = dA + 16384u;
#pragma unroll
        for (int i = 0; i < 4; i++) {
            int fidx = tid + i * 256;
            int row = fidx >> 3, cc = fidx & 7;
            uint32_t off = swz128((uint32_t)(row * 128 + cc * 16));
            cpa16(dA + off, Ap + (size_t)(m0 + row) * 1024 + kk + cc * 8);
            cpa16(dB + off, Bp + (size_t)(n0 + row) * 1024 + kk + cc * 8);
        }
        CP_COMMIT();
    };

    issue(0);
    for (int c = 0; c < 48; c++) {
        if (c + 1 < 48) { issue(c + 1); CP_WAIT(1); }
        else            { CP_WAIT(0); }
        __syncthreads();
        const uint32_t sA = sb + (uint32_t)(c & 1) * 32768u;
        const uint32_t sB = sA + 16384u;
#pragma unroll
        for (int s = 0; s < 4; s++) {
            uint32_t aF[2][4], bF[4][4];
            {
                const int row16 = (lane & 7) | (((lane >> 3) & 1) << 3);
                const int colb = ((lane >> 4) << 4) + s * 32;
#pragma unroll
                for (int mt = 0; mt < 2; mt++)
                    ldsm4(aF[mt], sA + swz128((uint32_t)(((wr * 32 + mt * 16 + row16) << 7) + colb)));
            }
            {
                const int row16 = (lane & 7) | ((lane >> 4) << 3);
                const int colb = (((lane >> 3) & 1) << 4) + s * 32;
#pragma unroll
                for (int p = 0; p < 4; p++)
                    ldsm4(bF[p], sB + swz128((uint32_t)(((wc * 64 + p * 16 + row16) << 7) + colb)));
            }
#pragma unroll
            for (int mt = 0; mt < 2; mt++)
#pragma unroll
                for (int nt = 0; nt < 8; nt++)
                    mma_bf16(acc[mt][nt], aF[mt], &bF[nt >> 1][(nt & 1) * 2]);
        }
        __syncthreads();
    }

    // epilogue
#pragma unroll
    for (int mt = 0; mt < 2; mt++) {
        const int r0 = m0 + wr * 32 + mt * 16 + (lane >> 2);
#pragma unroll
        for (int half = 0; half < 2; half++) {
            const int m = r0 + half * 8;
            const int b = m >> 11, s = m & 2047;
#pragma unroll
            for (int nt = 0; nt < 8; nt++) {
                const int n = n0 + wc * 64 + nt * 8 + (lane & 3) * 2;
                float v0 = acc[mt][nt][half * 2]     + __ldg(&bias[n]);
                float v1 = acc[mt][nt][half * 2 + 1] + __ldg(&bias[n + 1]);
                if (EPI == 1) {
                    float2 o = {v0, v1};
                    *(float2*)&Of[(size_t)m * Nout + n] = o;
                } else {
                    const int h = n >> 6, hd = n & 63;
                    float h0 = bfh(v0), h1 = bfh(v1);
                    size_t addr = (((size_t)b * H_ + h) * S_ + s) * HD_ + hd;
                    *(uint32_t*)&Oh[addr] = pack2(h0, h1);
                    *(uint32_t*)&Ol[addr] = pack2(v0 - h0, v1 - h1);
                }
            }
        }
    }
}

// ---------------- attention (mma.sync, FA2 layout, kv-tile 64) ----------------
// CTA: 128 q rows x one (b,h). 8 warps x 16 q rows, full 64-kv width per tile.
// smem: Qh 0..16K, Ql 16K..32K; stage st = 32K + (t&1)*32K:
//   Kh +0 (8K), Kl +8K, Vh +16K, Vl +24K     total 96KB -> 2 CTAs/SM
__global__ void __launch_bounds__(256, 2) attn_mma(
    const __nv_bfloat16* __restrict__ QH, const __nv_bfloat16* __restrict__ QL,
    const __nv_bfloat16* __restrict__ KH, const __nv_bfloat16* __restrict__ KL,
    const __nv_bfloat16* __restrict__ VH, const __nv_bfloat16* __restrict__ VL,
    __nv_bfloat16* __restrict__ CH, __nv_bfloat16* __restrict__ CL)
{
    extern __shared__ __align__(1024) char sm[];
    const uint32_t sb = smem_u32(sm);
    const int tid = threadIdx.x, wid = tid >> 5, lane = tid & 31;
    const int bh = blockIdx.x, q0 = blockIdx.y * 128;
    const size_t baseQ = (size_t)bh * S_ * HD_ + (size_t)q0 * HD_;
    const size_t baseK = (size_t)bh * S_ * HD_;

    auto issueKV = [&](int t) {
        const uint32_t st = sb + 32768u + (uint32_t)(t & 1) * 32768u;
#pragma unroll
        for (int i = 0; i < 2; i++) {
            int fidx = tid + i * 256;          // 0..511
            int r = fidx >> 3, cc = fidx & 7;
            uint32_t off = swz128((uint32_t)(r * 128 + cc * 16));
            const size_t src = baseK + (size_t)(t * 64 + r) * 64 + cc * 8;
            cpa16(st + off,           KH + src);
            cpa16(st + 8192u + off,   KL + src);
            cpa16(st + 16384u + off,  VH + src);
            cpa16(st + 24576u + off,  VL + src);
        }
        CP_COMMIT();
    };

    // prologue: Q tiles + stage 0
#pragma unroll
    for (int i = 0; i < 4; i++) {
        int fidx = tid + i * 256;
        int row = fidx >> 3, cc = fidx & 7;
        uint32_t off = swz128((uint32_t)(row * 128 + cc * 16));
        cpa16(sb + off,          QH + baseQ + (size_t)row * 64 + cc * 8);
        cpa16(sb + 16384u + off, QL + baseQ + (size_t)row * 64 + cc * 8);
    }
    CP_COMMIT();
    issueKV(0);
    CP_WAIT(1);
    __syncthreads();

    // Q fragments (A-operand), per warp rows wid*16..+15
    uint32_t qh[4][4], ql[4][4];
    {
        const int row16 = (lane & 7) | (((lane >> 3) & 1) << 3);
#pragma unroll
        for (int ds = 0; ds < 4; ds++) {
            const int colb = ((lane >> 4) << 4) + ds * 32;
            uint32_t off = swz128((uint32_t)(((wid * 16 + row16) << 7) + colb));
            ldsm4(qh[ds], sb + off);
            ldsm4(ql[ds], sb + 16384u + off);
        }
    }

    float accO[8][4];
#pragma unroll
    for (int i = 0; i < 8; i++)
#pragma unroll
        for (int j = 0; j < 4; j++) accO[i][j] = 0.0f;
    float rs0 = 0.0f, rs1 = 0.0f;

    const int rowB = (lane & 7) | ((lane >> 4) << 3);   // K B-operand ldsm row
    const int colBh = ((lane >> 3) & 1) << 4;
    const int rowV = lane & 15;                          // V trans-ldsm row
    const int colV = (lane >> 4) * 16;                   // bytes

    for (int t = 0; t < 32; t++) {
        if (t + 1 < 32) { issueKV(t + 1); CP_WAIT(1); }
        else            { CP_WAIT(0); }
        __syncthreads();
        const uint32_t st = sb + 32768u + (uint32_t)(t & 1) * 32768u;

        // S = Qh*Kh + Ql*Kh + Qh*Kl
        float accS[8][4];
#pragma unroll
        for (int i = 0; i < 8; i++)
#pragma unroll
            for (int j = 0; j < 4; j++) accS[i][j] = 0.0f;

#pragma unroll
        for (int ds = 0; ds < 4; ds++) {
            const int colb = colBh + ds * 32;
#pragma unroll
            for (int p = 0; p < 4; p++) {
                uint32_t bh_[4], bl_[4];
                uint32_t off = swz128((uint32_t)(((p * 16 + rowB) << 7) + colb));
                ldsm4(bh_, st + off);
                ldsm4(bl_, st + 8192u + off);
#pragma unroll
                for (int half = 0; half < 2; half++) {
                    const int nt = p * 2 + half;
                    mma_bf16(accS[nt], qh[ds], &bh_[half * 2]);
                    mma_bf16(accS[nt], ql[ds], &bh_[half * 2]);
                    mma_bf16(accS[nt], qh[ds], &bl_[half * 2]);
                }
            }
        }

        // exp + rowsum
#pragma unroll
        for (int nt = 0; nt < 8; nt++) {
            float e0 = __expf(accS[nt][0] * 0.125f);
            float e1 = __expf(accS[nt][1] * 0.125f);
            float e2 = __expf(accS[nt][2] * 0.125f);
            float e3 = __expf(accS[nt][3] * 0.125f);
            rs0 += e0 + e1; rs1 += e2 + e3;
            accS[nt][0] = e0; accS[nt][1] = e1; accS[nt][2] = e2; accS[nt][3] = e3;
        }

        // O += Ph*Vh + Pl*Vh + Ph*Vl   (V loaded natural via ldmatrix.trans)
#pragma unroll
        for (int p = 0; p < 4; p++) {
            uint32_t ah[4], al[4];
            {
                const float* c0 = accS[2 * p];
                const float* c1 = accS[2 * p + 1];
                float h00 = bfh(c0[0]), h01 = bfh(c0[1]), h02 = bfh(c0[2]), h03 = bfh(c0[3]);
                float h10 = bfh(c1[0]), h11 = bfh(c1[1]), h12 = bfh(c1[2]), h13 = bfh(c1[3]);
                ah[0] = pack2(h00, h01); ah[1] = pack2(h02, h03);
                ah[2] = pack2(h10, h11); ah[3] = pack2(h12, h13);
                al[0] = pack2(c0[0] - h00, c0[1] - h01); al[1] = pack2(c0[2] - h02, c0[3] - h03);
                al[2] = pack2(c1[0] - h10, c1[1] - h11); al[3] = pack2(c1[2] - h12, c1[3] - h13);
            }
#pragma unroll
            for (int jj = 0; jj < 4; jj++) {
                uint32_t vh_[4], vl_[4];
                uint32_t off = swz128((uint32_t)(((p * 16 + rowV) << 7) + jj * 32 + colV));
                ldsm4t(vh_, st + 16384u + off);
                ldsm4t(vl_, st + 24576u + off);
#pragma unroll
                for (int half = 0; half < 2; half++) {
                    const int nt = jj * 2 + half;
                    mma_bf16(accO[nt], ah, &vh_[half * 2]);
                    mma_bf16(accO[nt], al, &vh_[half * 2]);
                    mma_bf16(accO[nt], ah, &vl_[half * 2]);
                }
            }
        }
        __syncthreads();
    }

    // finalize
    rs0 += __shfl_xor_sync(0xffffffffu, rs0, 1);
    rs0 += __shfl_xor_sync(0xffffffffu, rs0, 2);
    rs1 += __shfl_xor_sync(0xffffffffu, rs1, 1);
    rs1 += __shfl_xor_sync(0xffffffffu, rs1, 2);
    const float inv0 = 1.0f / (1.0f + rs0);
    const float inv1 = 1.0f / (1.0f + rs1);

    const int b = bh >> 4, h = bh & 15;
    const int qA = q0 + wid * 16 + (lane >> 2);
#pragma unroll
    for (int half = 0; half < 2; half++) {
        const int q = qA + half * 8;
        const float inv = half ? inv1 : inv0;
        const size_t rowb = ((size_t)b * S_ + q) * D_ + h * HD_;
#pragma unroll
        for (int nt = 0; nt < 8; nt++) {
            const int col = nt * 8 + (lane & 3) * 2;
            float v0 = accO[nt][half * 2]     * inv;
            float v1 = accO[nt][half * 2 + 1] * inv;
            float h0 = bfh(v0), h1 = bfh(v1);
            *(uint32_t*)&CH[rowb + col] = pack2(h0, h1);
            *(uint32_t*)&CL[rowb + col] = pack2(v0 - h0, v1 - h1);
        }
    }
}

// ---------------- host ----------------
extern "C" void kernel_launch(void* const* d_in, const int* in_sizes, int n_in,
                              void* d_out, int out_size)
{
    (void)in_sizes; (void)n_in; (void)out_size;
    const float* query = (const float*)d_in[0];
    const float* key   = (const float*)d_in[1];
    const float* value = (const float*)d_in[2];
    const float* Wq = (const float*)d_in[3];
    const float* bq = (const float*)d_in[4];
    const float* Wk = (const float*)d_in[5];
    const float* bk = (const float*)d_in[6];
    const float* Wv = (const float*)d_in[7];
    const float* bv = (const float*)d_in[8];
    const float* Wf = (const float*)d_in[9];
    const float* bf = (const float*)d_in[10];

    __nv_bfloat16* G;
    cudaGetSymbolAddress((void**)&G, g_bf);

    const int n4 = (int)(SZX / 4);
    split_f32<<<n4 / 256, 256>>>(query, G + O_XQH, G + O_XQL, n4);
    split_f32<<<n4 / 256, 256>>>(key,   G + O_XKH, G + O_XKL, n4);
    split_f32<<<n4 / 256, 256>>>(value, G + O_XVH, G + O_XVL, n4);

    transpose_split<<<dim3(32, 32), 256>>>(Wq, G + O_WQH, G + O_WQL, D_, D_);
    transpose_split<<<dim3(32, 32), 256>>>(Wk, G + O_WKH, G + O_WKL, D_, D_);
    transpose_split<<<dim3(32, 32), 256>>>(Wv, G + O_WVH, G + O_WVL, D_, D_);
    transpose_split<<<dim3(8, 32),  256>>>(Wf, G + O_WFH, G + O_WFL, D_, OUT_);

    const int gsm = 65536;
    cudaFuncSetAttribute(gemm_mma<0>, cudaFuncAttributeMaxDynamicSharedMemorySize, gsm);
    cudaFuncSetAttribute(gemm_mma<1>, cudaFuncAttributeMaxDynamicSharedMemorySize, gsm);

    dim3 gP(D_ / 128, M_ / 128);  // (8, 64)
    gemm_mma<0><<<gP, 256, gsm>>>(G + O_XQH, G + O_XQL, G + O_WQH, G + O_WQL, bq,
                                  G + O_QH, G + O_QL, nullptr, D_);
    gemm_mma<0><<<gP, 256, gsm>>>(G + O_XKH, G + O_XKL, G + O_WKH, G + O_WKL, bk,
                                  G + O_KH, G + O_KL, nullptr, D_);
    gemm_mma<0><<<gP, 256, gsm>>>(G + O_XVH, G + O_XVL, G + O_WVH, G + O_WVL, bv,
                                  G + O_VH, G + O_VL, nullptr, D_);

    const int asm_ = 32768 + 2 * 32768;  // 98304
    cudaFuncSetAttribute(attn_mma, cudaFuncAttributeMaxDynamicSharedMemorySize, asm_);
    attn_mma<<<dim3(BH_, S_ / 128), 256, asm_>>>(
        G + O_QH, G + O_QL, G + O_KH, G + O_KL, G + O_VH, G + O_VL,
        G + O_CH, G + O_CL);

    dim3 gF(OUT_ / 128, M_ / 128);  // (2, 64)
    gemm_mma<1><<<gF, 256, gsm>>>(G + O_CH, G + O_CL, G + O_WFH, G + O_WFL, bf,
                                  nullptr, nullptr, (float*)d_out, OUT_);
}

// round 7
// speedup vs baseline: 4.6453x; 1.3864x over previous
#include <cuda_runtime.h>
#include <cuda_fp16.h>
#include <cstdint>

#define B_ 4
#define S_ 2048
#define D_ 1024
#define H_ 16
#define HD_ 64
#define OUT_ 256
#define M_ (B_*S_)
#define BH_ (B_*H_)

static constexpr size_t SZX = (size_t)M_ * D_;
static constexpr size_t SZW = (size_t)D_ * D_;
static constexpr size_t SZF = (size_t)D_ * OUT_;

static constexpr size_t O_XQH = 0,            O_XQL = O_XQH + SZX;
static constexpr size_t O_XKH = O_XQL + SZX,  O_XKL = O_XKH + SZX;
static constexpr size_t O_XVH = O_XKL + SZX,  O_XVL = O_XVH + SZX;
static constexpr size_t O_WQH = O_XVL + SZX;
static constexpr size_t O_WKH = O_WQH + SZW;
static constexpr size_t O_WVH = O_WKH + SZW;
static constexpr size_t O_WFH = O_WVH + SZW;
static constexpr size_t O_QH  = O_WFH + SZF,  O_QL  = O_QH + SZX;
static constexpr size_t O_KH  = O_QL + SZX;
static constexpr size_t O_VH  = O_KH + SZX;
static constexpr size_t O_CH  = O_VH + SZX,   O_CL  = O_CH + SZX;
static constexpr size_t TOTAL_HF = O_CL + SZX;

__device__ __half g_hf[TOTAL_HF];

// ---------------- helpers ----------------
__device__ __forceinline__ uint32_t smem_u32(const void* p) {
    uint32_t a;
    asm("{ .reg .u64 t; cvta.to.shared.u64 t, %1; cvt.u32.u64 %0, t; }" : "=r"(a) : "l"(p));
    return a;
}
__device__ __forceinline__ void ldsm4(uint32_t* r, uint32_t a) {
    asm volatile("ldmatrix.sync.aligned.m8n8.x4.shared.b16 {%0,%1,%2,%3}, [%4];"
        : "=r"(r[0]), "=r"(r[1]), "=r"(r[2]), "=r"(r[3]) : "r"(a));
}
__device__ __forceinline__ void ldsm4t(uint32_t* r, uint32_t a) {
    asm volatile("ldmatrix.sync.aligned.m8n8.x4.trans.shared.b16 {%0,%1,%2,%3}, [%4];"
        : "=r"(r[0]), "=r"(r[1]), "=r"(r[2]), "=r"(r[3]) : "r"(a));
}
__device__ __forceinline__ void mma_f16(float* d, const uint32_t* a, const uint32_t* b) {
    asm volatile("mma.sync.aligned.m16n8k16.row.col.f32.f16.f16.f32 "
        "{%0,%1,%2,%3}, {%4,%5,%6,%7}, {%8,%9}, {%0,%1,%2,%3};"
        : "+f"(d[0]), "+f"(d[1]), "+f"(d[2]), "+f"(d[3])
        : "r"(a[0]), "r"(a[1]), "r"(a[2]), "r"(a[3]), "r"(b[0]), "r"(b[1]));
}
__device__ __forceinline__ void cpa16(uint32_t dst, const void* src) {
    asm volatile("cp.async.cg.shared.global [%0], [%1], 16;" :: "r"(dst), "l"(src));
}
#define CP_COMMIT() asm volatile("cp.async.commit_group;" ::: "memory")
#define CP_WAIT(n)  asm volatile("cp.async.wait_group %0;" :: "n"(n) : "memory")

__device__ __forceinline__ uint32_t swz128(uint32_t o) { return o ^ ((o >> 3) & 0x70); }
__device__ __forceinline__ uint32_t pack2h(float a, float b) {
    __half2 t = __floats2half2_rn(a, b);
    return *(uint32_t*)&t;
}
__device__ __forceinline__ float fhh(float v) {
    return __half2float(__float2half_rn(v));
}

// ---------------- conversions ----------------
__global__ void split_f32(const float* __restrict__ x,
                          __half* __restrict__ hi,
                          __half* __restrict__ lo, int n4) {
    int i = blockIdx.x * blockDim.x + threadIdx.x;
    if (i >= n4) return;
    float4 v = ((const float4*)x)[i];
    float a[4] = {v.x, v.y, v.z, v.w};
    float h[4];
#pragma unroll
    for (int j = 0; j < 4; j++) h[j] = fhh(a[j]);
    ((uint32_t*)hi)[i*2]   = pack2h(h[0], h[1]);
    ((uint32_t*)hi)[i*2+1] = pack2h(h[2], h[3]);
    ((uint32_t*)lo)[i*2]   = pack2h(a[0]-h[0], a[1]-h[1]);
    ((uint32_t*)lo)[i*2+1] = pack2h(a[2]-h[2], a[3]-h[3]);
}

// W [K][N] -> W^T hi plane [N][K] (fp16 round)
__global__ void transpose_h(const float* __restrict__ W,
                            __half* __restrict__ Th,
                            int Kdim, int Ndim) {
    __shared__ float t[32][33];
    const int n0 = blockIdx.x * 32, k0 = blockIdx.y * 32;
    const int tx = threadIdx.x & 31, ty = threadIdx.x >> 5;
#pragma unroll
    for (int i = 0; i < 32; i += 8)
        t[ty + i][tx] = W[(size_t)(k0 + ty + i) * Ndim + n0 + tx];
    __syncthreads();
#pragma unroll
    for (int i = 0; i < 32; i += 8)
        Th[(size_t)(n0 + ty + i) * Kdim + k0 + tx] = __float2half_rn(t[tx][ty + i]);
}

// ---------------- mma.sync fp16 2-phase GEMM ----------------
// C[128,128] = (Ah+Al)[128,1024] @ Bh[n][k]^T  (K_eff = 2048)
// EPI 0: heads hi+lo planes; EPI 1: fp32 row-major; EPI 2: heads hi only
template<int EPI>
__global__ void __launch_bounds__(256, 2) gemm_mma(
    const __half* __restrict__ Ah, const __half* __restrict__ Al,
    const __half* __restrict__ Bh,
    const float* __restrict__ bias,
    __half* __restrict__ Oh, __half* __restrict__ Ol,
    float* __restrict__ Of, int Nout)
{
    extern __shared__ __align__(1024) char sm[];
    const uint32_t sb = smem_u32(sm);
    const int tid = threadIdx.x, wid = tid >> 5, lane = tid & 31;
    const int m0 = blockIdx.y * 128, n0 = blockIdx.x * 128;
    const int wr = wid >> 1, wc = wid & 1;

    float acc[2][8][4];
#pragma unroll
    for (int i = 0; i < 2; i++)
#pragma unroll
        for (int j = 0; j < 8; j++)
#pragma unroll
            for (int q = 0; q < 4; q++) acc[i][j][q] = 0.0f;

    auto issue = [&](int c) {
        const int ph = c >> 4, kk = (c & 15) * 64;
        const __half* Ap = ph ? Al : Ah;
        const uint32_t dA = sb + (uint32_t)(c & 1) * 32768u;
        const uint32_t dB = dA + 16384u;
#pragma unroll
        for (int i = 0; i < 4; i++) {
            int fidx = tid + i * 256;
            int row = fidx >> 3, cc = fidx & 7;
            uint32_t off = swz128((uint32_t)(row * 128 + cc * 16));
            cpa16(dA + off, Ap + (size_t)(m0 + row) * 1024 + kk + cc * 8);
            cpa16(dB + off, Bh + (size_t)(n0 + row) * 1024 + kk + cc * 8);
        }
        CP_COMMIT();
    };

    issue(0);
    for (int c = 0; c < 32; c++) {
        if (c + 1 < 32) { issue(c + 1); CP_WAIT(1); }
        else            { CP_WAIT(0); }
        __syncthreads();
        const uint32_t sA = sb + (uint32_t)(c & 1) * 32768u;
        const uint32_t sB = sA + 16384u;
#pragma unroll
        for (int s = 0; s < 4; s++) {
            uint32_t aF[2][4], bF[4][4];
            {
                const int row16 = (lane & 7) | (((lane >> 3) & 1) << 3);
                const int colb = ((lane >> 4) << 4) + s * 32;
#pragma unroll
                for (int mt = 0; mt < 2; mt++)
                    ldsm4(aF[mt], sA + swz128((uint32_t)(((wr * 32 + mt * 16 + row16) << 7) + colb)));
            }
            {
                const int row16 = (lane & 7) | ((lane >> 4) << 3);
                const int colb = (((lane >> 3) & 1) << 4) + s * 32;
#pragma unroll
                for (int p = 0; p < 4; p++)
                    ldsm4(bF[p], sB + swz128((uint32_t)(((wc * 64 + p * 16 + row16) << 7) + colb)));
            }
#pragma unroll
            for (int mt = 0; mt < 2; mt++)
#pragma unroll
                for (int nt = 0; nt < 8; nt++)
                    mma_f16(acc[mt][nt], aF[mt], &bF[nt >> 1][(nt & 1) * 2]);
        }
        __syncthreads();
    }

    // epilogue
#pragma unroll
    for (int mt = 0; mt < 2; mt++) {
        const int r0 = m0 + wr * 32 + mt * 16 + (lane >> 2);
#pragma unroll
        for (int half = 0; half < 2; half++) {
            const int m = r0 + half * 8;
            const int b = m >> 11, s = m & 2047;
#pragma unroll
            for (int nt = 0; nt < 8; nt++) {
                const int n = n0 + wc * 64 + nt * 8 + (lane & 3) * 2;
                float v0 = acc[mt][nt][half * 2]     + __ldg(&bias[n]);
                float v1 = acc[mt][nt][half * 2 + 1] + __ldg(&bias[n + 1]);
                if (EPI == 1) {
                    float2 o = {v0, v1};
                    *(float2*)&Of[(size_t)m * Nout + n] = o;
                } else if (EPI == 0) {
                    const int h = n >> 6, hd = n & 63;
                    float h0 = fhh(v0), h1 = fhh(v1);
                    size_t addr = (((size_t)b * H_ + h) * S_ + s) * HD_ + hd;
                    *(uint32_t*)&Oh[addr] = pack2h(h0, h1);
                    *(uint32_t*)&Ol[addr] = pack2h(v0 - h0, v1 - h1);
                } else {
                    const int h = n >> 6, hd = n & 63;
                    size_t addr = (((size_t)b * H_ + h) * S_ + s) * HD_ + hd;
                    *(uint32_t*)&Oh[addr] = pack2h(v0, v1);
                }
            }
        }
    }
}

// ---------------- attention (fp16 2-MMA, kv-tile 64) ----------------
// smem: Qh 0..16K, Ql 16K..32K; stage st = 32K + (t&1)*16K: Kh +0, Vh +8K
// total 64KB -> 2+ CTAs/SM
__global__ void __launch_bounds__(256, 2) attn_mma(
    const __half* __restrict__ QH, const __half* __restrict__ QL,
    const __half* __restrict__ KH, const __half* __restrict__ VH,
    __half* __restrict__ CH, __half* __restrict__ CL)
{
    extern __shared__ __align__(1024) char sm[];
    const uint32_t sb = smem_u32(sm);
    const int tid = threadIdx.x, wid = tid >> 5, lane = tid & 31;
    const int bh = blockIdx.x, q0 = blockIdx.y * 128;
    const size_t baseQ = (size_t)bh * S_ * HD_ + (size_t)q0 * HD_;
    const size_t baseK = (size_t)bh * S_ * HD_;

    auto issueKV = [&](int t) {
        const uint32_t st = sb + 32768u + (uint32_t)(t & 1) * 16384u;
#pragma unroll
        for (int i = 0; i < 2; i++) {
            int fidx = tid + i * 256;          // 0..511
            int r = fidx >> 3, cc = fidx & 7;
            uint32_t off = swz128((uint32_t)(r * 128 + cc * 16));
            const size_t src = baseK + (size_t)(t * 64 + r) * 64 + cc * 8;
            cpa16(st + off,         KH + src);
            cpa16(st + 8192u + off, VH + src);
        }
        CP_COMMIT();
    };

    // prologue: Q tiles + stage 0
#pragma unroll
    for (int i = 0; i < 4; i++) {
        int fidx = tid + i * 256;
        int row = fidx >> 3, cc = fidx & 7;
        uint32_t off = swz128((uint32_t)(row * 128 + cc * 16));
        cpa16(sb + off,          QH + baseQ + (size_t)row * 64 + cc * 8);
        cpa16(sb + 16384u + off, QL + baseQ + (size_t)row * 64 + cc * 8);
    }
    CP_COMMIT();
    issueKV(0);
    CP_WAIT(1);
    __syncthreads();

    // Q fragments (A-operand), per warp rows wid*16..+15
    uint32_t qh[4][4], ql[4][4];
    {
        const int row16 = (lane & 7) | (((lane >> 3) & 1) << 3);
#pragma unroll
        for (int ds = 0; ds < 4; ds++) {
            const int colb = ((lane >> 4) << 4) + ds * 32;
            uint32_t off = swz128((uint32_t)(((wid * 16 + row16) << 7) + colb));
            ldsm4(qh[ds], sb + off);
            ldsm4(ql[ds], sb + 16384u + off);
        }
    }

    float accO[8][4];
#pragma unroll
    for (int i = 0; i < 8; i++)
#pragma unroll
        for (int j = 0; j < 4; j++) accO[i][j] = 0.0f;
    float rs0 = 0.0f, rs1 = 0.0f;

    const int rowB = (lane & 7) | ((lane >> 4) << 3);   // K B-operand ldsm row
    const int colBh = ((lane >> 3) & 1) << 4;
    const int rowV = lane & 15;                          // V trans-ldsm row
    const int colV = (lane >> 4) * 16;                   // bytes

    for (int t = 0; t < 32; t++) {
        if (t + 1 < 32) { issueKV(t + 1); CP_WAIT(1); }
        else            { CP_WAIT(0); }
        __syncthreads();
        const uint32_t st = sb + 32768u + (uint32_t)(t & 1) * 16384u;

        // S = (Qh + Ql) * Kh
        float accS[8][4];
#pragma unroll
        for (int i = 0; i < 8; i++)
#pragma unroll
            for (int j = 0; j < 4; j++) accS[i][j] = 0.0f;

#pragma unroll
        for (int ds = 0; ds < 4; ds++) {
            const int colb = colBh + ds * 32;
#pragma unroll
            for (int p = 0; p < 4; p++) {
                uint32_t bh_[4];
                uint32_t off = swz128((uint32_t)(((p * 16 + rowB) << 7) + colb));
                ldsm4(bh_, st + off);
#pragma unroll
                for (int half = 0; half < 2; half++) {
                    const int nt = p * 2 + half;
                    mma_f16(accS[nt], qh[ds], &bh_[half * 2]);
                    mma_f16(accS[nt], ql[ds], &bh_[half * 2]);
                }
            }
        }

        // exp + rowsum
#pragma unroll
        for (int nt = 0; nt < 8; nt++) {
            float e0 = __expf(accS[nt][0] * 0.125f);
            float e1 = __expf(accS[nt][1] * 0.125f);
            float e2 = __expf(accS[nt][2] * 0.125f);
            float e3 = __expf(accS[nt][3] * 0.125f);
            rs0 += e0 + e1; rs1 += e2 + e3;
            accS[nt][0] = e0; accS[nt][1] = e1; accS[nt][2] = e2; accS[nt][3] = e3;
        }

        // O += (Ph + Pl) * Vh   (V natural via ldmatrix.trans)
#pragma unroll
        for (int p = 0; p < 4; p++) {
            uint32_t ah[4], al[4];
            {
                const float* c0 = accS[2 * p];
                const float* c1 = accS[2 * p + 1];
                float h00 = fhh(c0[0]), h01 = fhh(c0[1]), h02 = fhh(c0[2]), h03 = fhh(c0[3]);
                float h10 = fhh(c1[0]), h11 = fhh(c1[1]), h12 = fhh(c1[2]), h13 = fhh(c1[3]);
                ah[0] = pack2h(h00, h01); ah[1] = pack2h(h02, h03);
                ah[2] = pack2h(h10, h11); ah[3] = pack2h(h12, h13);
                al[0] = pack2h(c0[0] - h00, c0[1] - h01); al[1] = pack2h(c0[2] - h02, c0[3] - h03);
                al[2] = pack2h(c1[0] - h10, c1[1] - h11); al[3] = pack2h(c1[2] - h12, c1[3] - h13);
            }
#pragma unroll
            for (int jj = 0; jj < 4; jj++) {
                uint32_t vh_[4];
                uint32_t off = swz128((uint32_t)(((p * 16 + rowV) << 7) + jj * 32 + colV));
                ldsm4t(vh_, st + 8192u + off);
#pragma unroll
                for (int half = 0; half < 2; half++) {
                    const int nt = jj * 2 + half;
                    mma_f16(accO[nt], ah, &vh_[half * 2]);
                    mma_f16(accO[nt], al, &vh_[half * 2]);
                }
            }
        }
        __syncthreads();
    }

    // finalize
    rs0 += __shfl_xor_sync(0xffffffffu, rs0, 1);
    rs0 += __shfl_xor_sync(0xffffffffu, rs0, 2);
    rs1 += __shfl_xor_sync(0xffffffffu, rs1, 1);
    rs1 += __shfl_xor_sync(0xffffffffu, rs1, 2);
    const float inv0 = 1.0f / (1.0f + rs0);
    const float inv1 = 1.0f / (1.0f + rs1);

    const int b = bh >> 4, h = bh & 15;
    const int qA = q0 + wid * 16 + (lane >> 2);
#pragma unroll
    for (int half = 0; half < 2; half++) {
        const int q = qA + half * 8;
        const float inv = half ? inv1 : inv0;
        const size_t rowb = ((size_t)b * S_ + q) * D_ + h * HD_;
#pragma unroll
        for (int nt = 0; nt < 8; nt++) {
            const int col = nt * 8 + (lane & 3) * 2;
            float v0 = accO[nt][half * 2]     * inv;
            float v1 = accO[nt][half * 2 + 1] * inv;
            float h0 = fhh(v0), h1 = fhh(v1);
            *(uint32_t*)&CH[rowb + col] = pack2h(h0, h1);
            *(uint32_t*)&CL[rowb + col] = pack2h(v0 - h0, v1 - h1);
        }
    }
}

// ---------------- host ----------------
extern "C" void kernel_launch(void* const* d_in, const int* in_sizes, int n_in,
                              void* d_out, int out_size)
{
    (void)in_sizes; (void)n_in; (void)out_size;
    const float* query = (const float*)d_in[0];
    const float* key   = (const float*)d_in[1];
    const float* value = (const float*)d_in[2];
    const float* Wq = (const float*)d_in[3];
    const float* bq = (const float*)d_in[4];
    const float* Wk = (const float*)d_in[5];
    const float* bk = (const float*)d_in[6];
    const float* Wv = (const float*)d_in[7];
    const float* bv = (const float*)d_in[8];
    const float* Wf = (const float*)d_in[9];
    const float* bf = (const float*)d_in[10];

    __half* G;
    cudaGetSymbolAddress((void**)&G, g_hf);

    const int n4 = (int)(SZX / 4);
    split_f32<<<n4 / 256, 256>>>(query, G + O_XQH, G + O_XQL, n4);
    split_f32<<<n4 / 256, 256>>>(key,   G + O_XKH, G + O_XKL, n4);
    split_f32<<<n4 / 256, 256>>>(value, G + O_XVH, G + O_XVL, n4);

    transpose_h<<<dim3(32, 32), 256>>>(Wq, G + O_WQH, D_, D_);
    transpose_h<<<dim3(32, 32), 256>>>(Wk, G + O_WKH, D_, D_);
    transpose_h<<<dim3(32, 32), 256>>>(Wv, G + O_WVH, D_, D_);
    transpose_h<<<dim3(8, 32),  256>>>(Wf, G + O_WFH, D_, OUT_);

    const int gsm = 65536;
    cudaFuncSetAttribute(gemm_mma<0>, cudaFuncAttributeMaxDynamicSharedMemorySize, gsm);
    cudaFuncSetAttribute(gemm_mma<1>, cudaFuncAttributeMaxDynamicSharedMemorySize, gsm);
    cudaFuncSetAttribute(gemm_mma<2>, cudaFuncAttributeMaxDynamicSharedMemorySize, gsm);

    dim3 gP(D_ / 128, M_ / 128);  // (8, 64)
    gemm_mma<0><<<gP, 256, gsm>>>(G + O_XQH, G + O_XQL, G + O_WQH, bq,
                                  G + O_QH, G + O_QL, nullptr, D_);
    gemm_mma<2><<<gP, 256, gsm>>>(G + O_XKH, G + O_XKL, G + O_WKH, bk,
                                  G + O_KH, nullptr, nullptr, D_);
    gemm_mma<2><<<gP, 256, gsm>>>(G + O_XVH, G + O_XVL, G + O_WVH, bv,
                                  G + O_VH, nullptr, nullptr, D_);

    const int asm_ = 32768 + 2 * 16384;  // 65536
    cudaFuncSetAttribute(attn_mma, cudaFuncAttributeMaxDynamicSharedMemorySize, asm_);
    attn_mma<<<dim3(BH_, S_ / 128), 256, asm_>>>(
        G + O_QH, G + O_QL, G + O_KH, G + O_VH, G + O_CH, G + O_CL);

    dim3 gF(OUT_ / 128, M_ / 128);  // (2, 64)
    gemm_mma<1><<<gF, 256, gsm>>>(G + O_CH, G + O_CL, G + O_WFH, bf,
                                  nullptr, nullptr, (float*)d_out, OUT_);
}

// round 8
// speedup vs baseline: 5.7818x; 1.2447x over previous
#include <cuda_runtime.h>
#include <cuda_fp16.h>
#include <cstdint>

#define B_ 4
#define S_ 2048
#define D_ 1024
#define H_ 16
#define HD_ 64
#define OUT_ 256
#define M_ (B_*S_)
#define BH_ (B_*H_)

static constexpr size_t SZX = (size_t)M_ * D_;
static constexpr size_t SZW = (size_t)D_ * D_;
static constexpr size_t SZF = (size_t)D_ * OUT_;

// x planes: [XQH,XQL, XKH,XKL, XVH,XVL] stride 2*SZX per input
static constexpr size_t O_X   = 0;
static constexpr size_t O_W   = O_X + 6 * SZX;          // [WQ,WK,WV] stride SZW
static constexpr size_t O_WF  = O_W + 3 * SZW;
static constexpr size_t O_QH  = O_WF + SZF,  O_QL = O_QH + SZX;
static constexpr size_t O_KH  = O_QL + SZX;
static constexpr size_t O_VH  = O_KH + SZX;
static constexpr size_t O_CH  = O_VH + SZX;
static constexpr size_t TOTAL_HF = O_CH + SZX;

__device__ __half g_hf[TOTAL_HF];

// ---------------- helpers ----------------
__device__ __forceinline__ uint32_t smem_u32(const void* p) {
    uint32_t a;
    asm("{ .reg .u64 t; cvta.to.shared.u64 t, %1; cvt.u32.u64 %0, t; }" : "=r"(a) : "l"(p));
    return a;
}
__device__ __forceinline__ void ldsm4(uint32_t* r, uint32_t a) {
    asm volatile("ldmatrix.sync.aligned.m8n8.x4.shared.b16 {%0,%1,%2,%3}, [%4];"
        : "=r"(r[0]), "=r"(r[1]), "=r"(r[2]), "=r"(r[3]) : "r"(a));
}
__device__ __forceinline__ void ldsm4t(uint32_t* r, uint32_t a) {
    asm volatile("ldmatrix.sync.aligned.m8n8.x4.trans.shared.b16 {%0,%1,%2,%3}, [%4];"
        : "=r"(r[0]), "=r"(r[1]), "=r"(r[2]), "=r"(r[3]) : "r"(a));
}
__device__ __forceinline__ void mma_f16(float* d, const uint32_t* a, const uint32_t* b) {
    asm volatile("mma.sync.aligned.m16n8k16.row.col.f32.f16.f16.f32 "
        "{%0,%1,%2,%3}, {%4,%5,%6,%7}, {%8,%9}, {%0,%1,%2,%3};"
        : "+f"(d[0]), "+f"(d[1]), "+f"(d[2]), "+f"(d[3])
        : "r"(a[0]), "r"(a[1]), "r"(a[2]), "r"(a[3]), "r"(b[0]), "r"(b[1]));
}
__device__ __forceinline__ void cpa16(uint32_t dst, const void* src) {
    asm volatile("cp.async.cg.shared.global [%0], [%1], 16;" :: "r"(dst), "l"(src));
}
#define CP_COMMIT() asm volatile("cp.async.commit_group;" ::: "memory")
#define CP_WAIT(n)  asm volatile("cp.async.wait_group %0;" :: "n"(n) : "memory")

__device__ __forceinline__ uint32_t swz128(uint32_t o) { return o ^ ((o >> 3) & 0x70); }
__device__ __forceinline__ uint32_t pack2h(float a, float b) {
    __half2 t = __floats2half2_rn(a, b);
    return *(uint32_t*)&t;
}
__device__ __forceinline__ float fhh(float v) {
    return __half2float(__float2half_rn(v));
}

// ---------------- conversions ----------------
__global__ void split_f32(const float* __restrict__ x,
                          __half* __restrict__ hi,
                          __half* __restrict__ lo, int n4) {
    int i = blockIdx.x * blockDim.x + threadIdx.x;
    if (i >= n4) return;
    float4 v = ((const float4*)x)[i];
    float a[4] = {v.x, v.y, v.z, v.w};
    float h[4];
#pragma unroll
    for (int j = 0; j < 4; j++) h[j] = fhh(a[j]);
    ((uint32_t*)hi)[i*2]   = pack2h(h[0], h[1]);
    ((uint32_t*)hi)[i*2+1] = pack2h(h[2], h[3]);
    ((uint32_t*)lo)[i*2]   = pack2h(a[0]-h[0], a[1]-h[1]);
    ((uint32_t*)lo)[i*2+1] = pack2h(a[2]-h[2], a[3]-h[3]);
}

__global__ void transpose_h(const float* __restrict__ W,
                            __half* __restrict__ Th,
                            int Kdim, int Ndim) {
    __shared__ float t[32][33];
    const int n0 = blockIdx.x * 32, k0 = blockIdx.y * 32;
    const int tx = threadIdx.x & 31, ty = threadIdx.x >> 5;
#pragma unroll
    for (int i = 0; i < 32; i += 8)
        t[ty + i][tx] = W[(size_t)(k0 + ty + i) * Ndim + n0 + tx];
    __syncthreads();
#pragma unroll
    for (int i = 0; i < 32; i += 8)
        Th[(size_t)(n0 + ty + i) * Kdim + k0 + tx] = __float2half_rn(t[tx][ty + i]);
}

// ---------------- shared GEMM mainloop body (macro-free via template) ---------
// computes acc[2][8][4] for C tile (m0,n0), A = (phases) @ Bh^T
template<int NPH>
__device__ __forceinline__ void gemm_body(
    float acc[2][8][4], const __half* Ah, const __half* Al, const __half* Bh,
    uint32_t sb, int m0, int n0, int tid, int wr, int wc, int lane)
{
    auto issue = [&](int c) {
        const int ph = c >> 4, kk = (c & 15) * 64;
        const __half* Ap = ph ? Al : Ah;
        const uint32_t dA = sb + (uint32_t)(c & 1) * 32768u;
        const uint32_t dB = dA + 16384u;
#pragma unroll
        for (int i = 0; i < 4; i++) {
            int fidx = tid + i * 256;
            int row = fidx >> 3, cc = fidx & 7;
            uint32_t off = swz128((uint32_t)(row * 128 + cc * 16));
            cpa16(dA + off, Ap + (size_t)(m0 + row) * 1024 + kk + cc * 8);
            cpa16(dB + off, Bh + (size_t)(n0 + row) * 1024 + kk + cc * 8);
        }
        CP_COMMIT();
    };

    issue(0);
    const int NC = NPH * 16;
    for (int c = 0; c < NC; c++) {
        if (c + 1 < NC) { issue(c + 1); CP_WAIT(1); }
        else            { CP_WAIT(0); }
        __syncthreads();
        const uint32_t sA = sb + (uint32_t)(c & 1) * 32768u;
        const uint32_t sB = sA + 16384u;
#pragma unroll
        for (int s = 0; s < 4; s++) {
            uint32_t aF[2][4], bF[4][4];
            {
                const int row16 = (lane & 7) | (((lane >> 3) & 1) << 3);
                const int colb = ((lane >> 4) << 4) + s * 32;
#pragma unroll
                for (int mt = 0; mt < 2; mt++)
                    ldsm4(aF[mt], sA + swz128((uint32_t)(((wr * 32 + mt * 16 + row16) << 7) + colb)));
            }
            {
                const int row16 = (lane & 7) | ((lane >> 4) << 3);
                const int colb = (((lane >> 3) & 1) << 4) + s * 32;
#pragma unroll
                for (int p = 0; p < 4; p++)
                    ldsm4(bF[p], sB + swz128((uint32_t)(((wc * 64 + p * 16 + row16) << 7) + colb)));
            }
#pragma unroll
            for (int mt = 0; mt < 2; mt++)
#pragma unroll
                for (int nt = 0; nt < 8; nt++)
                    mma_f16(acc[mt][nt], aF[mt], &bF[nt >> 1][(nt & 1) * 2]);
        }
        __syncthreads();
    }
}

// ---------------- merged QKV projection (grid.z = 0:Q, 1:K, 2:V) -------------
__global__ void __launch_bounds__(256, 2) proj_mma(
    __half* __restrict__ G,
    const float* __restrict__ bq, const float* __restrict__ bk,
    const float* __restrict__ bv)
{
    extern __shared__ __align__(1024) char sm[];
    const uint32_t sb = smem_u32(sm);
    const int tid = threadIdx.x, wid = tid >> 5, lane = tid & 31;
    const int m0 = blockIdx.y * 128, n0 = blockIdx.x * 128;
    const int z = blockIdx.z;
    const int wr = wid >> 1, wc = wid & 1;

    const __half* Ah = G + O_X + (size_t)z * 2 * SZX;
    const __half* Al = Ah + SZX;
    const __half* Bh = G + O_W + (size_t)z * SZW;
    const float* bias = (z == 0) ? bq : (z == 1) ? bk : bv;

    float acc[2][8][4];
#pragma unroll
    for (int i = 0; i < 2; i++)
#pragma unroll
        for (int j = 0; j < 8; j++)
#pragma unroll
            for (int q = 0; q < 4; q++) acc[i][j][q] = 0.0f;

    gemm_body<2>(acc, Ah, Al, Bh, sb, m0, n0, tid, wr, wc, lane);

    __half* Oh = (z == 0) ? (G + O_QH) : (z == 1) ? (G + O_KH) : (G + O_VH);
    __half* Ol = G + O_QL;
    const float scale = (z == 0) ? 0.125f : 1.0f;

#pragma unroll
    for (int mt = 0; mt < 2; mt++) {
        const int r0 = m0 + wr * 32 + mt * 16 + (lane >> 2);
#pragma unroll
        for (int half = 0; half < 2; half++) {
            const int m = r0 + half * 8;
            const int b = m >> 11, s = m & 2047;
#pragma unroll
            for (int nt = 0; nt < 8; nt++) {
                const int n = n0 + wc * 64 + nt * 8 + (lane & 3) * 2;
                float v0 = (acc[mt][nt][half * 2]     + __ldg(&bias[n]))     * scale;
                float v1 = (acc[mt][nt][half * 2 + 1] + __ldg(&bias[n + 1])) * scale;
                const int h = n >> 6, hd = n & 63;
                size_t addr = (((size_t)b * H_ + h) * S_ + s) * HD_ + hd;
                if (z == 0) {
                    float h0 = fhh(v0), h1 = fhh(v1);
                    *(uint32_t*)&Oh[addr] = pack2h(h0, h1);
                    *(uint32_t*)&Ol[addr] = pack2h(v0 - h0, v1 - h1);
                } else {
                    *(uint32_t*)&Oh[addr] = pack2h(v0, v1);
                }
            }
        }
    }
}

// ---------------- final GEMM: out = Ch @ Wf^T + bf (fp32 out) ----------------
__global__ void __launch_bounds__(256, 2) final_mma(
    const __half* __restrict__ Ch, const __half* __restrict__ WfT,
    const float* __restrict__ bias, float* __restrict__ Of)
{
    extern __shared__ __align__(1024) char sm[];
    const uint32_t sb = smem_u32(sm);
    const int tid = threadIdx.x, wid = tid >> 5, lane = tid & 31;
    const int m0 = blockIdx.y * 128, n0 = blockIdx.x * 128;
    const int wr = wid >> 1, wc = wid & 1;

    float acc[2][8][4];
#pragma unroll
    for (int i = 0; i < 2; i++)
#pragma unroll
        for (int j = 0; j < 8; j++)
#pragma unroll
            for (int q = 0; q < 4; q++) acc[i][j][q] = 0.0f;

    gemm_body<1>(acc, Ch, nullptr, WfT, sb, m0, n0, tid, wr, wc, lane);

#pragma unroll
    for (int mt = 0; mt < 2; mt++) {
        const int r0 = m0 + wr * 32 + mt * 16 + (lane >> 2);
#pragma unroll
        for (int half = 0; half < 2; half++) {
            const int m = r0 + half * 8;
#pragma unroll
            for (int nt = 0; nt < 8; nt++) {
                const int n = n0 + wc * 64 + nt * 8 + (lane & 3) * 2;
                float2 o;
                o.x = acc[mt][nt][half * 2]     + __ldg(&bias[n]);
                o.y = acc[mt][nt][half * 2 + 1] + __ldg(&bias[n + 1]);
                *(float2*)&Of[(size_t)m * OUT_ + n] = o;
            }
        }
    }
}

// ---------------- attention ----------------
// smem: Qh 0..16K, Ql 16K..32K; stage st = 32K + (t&1)*16K: Kh +0, Vh +8K
__global__ void __launch_bounds__(256, 2) attn_mma(
    const __half* __restrict__ QH, const __half* __restrict__ QL,
    const __half* __restrict__ KH, const __half* __restrict__ VH,
    __half* __restrict__ CH)
{
    extern __shared__ __align__(1024) char sm[];
    const uint32_t sb = smem_u32(sm);
    const int tid = threadIdx.x, wid = tid >> 5, lane = tid & 31;
    const int bh = blockIdx.x, q0 = blockIdx.y * 128;
    const size_t baseQ = (size_t)bh * S_ * HD_ + (size_t)q0 * HD_;
    const size_t baseK = (size_t)bh * S_ * HD_;

    auto issueKV = [&](int t) {
        const uint32_t st = sb + 32768u + (uint32_t)(t & 1) * 16384u;
#pragma unroll
        for (int i = 0; i < 2; i++) {
            int fidx = tid + i * 256;
            int r = fidx >> 3, cc = fidx & 7;
            uint32_t off = swz128((uint32_t)(r * 128 + cc * 16));
            const size_t src = baseK + (size_t)(t * 64 + r) * 64 + cc * 8;
            cpa16(st + off,         KH + src);
            cpa16(st + 8192u + off, VH + src);
        }
        CP_COMMIT();
    };

#pragma unroll
    for (int i = 0; i < 4; i++) {
        int fidx = tid + i * 256;
        int row = fidx >> 3, cc = fidx & 7;
        uint32_t off = swz128((uint32_t)(row * 128 + cc * 16));
        cpa16(sb + off,          QH + baseQ + (size_t)row * 64 + cc * 8);
        cpa16(sb + 16384u + off, QL + baseQ + (size_t)row * 64 + cc * 8);
    }
    CP_COMMIT();
    issueKV(0);
    CP_WAIT(1);
    __syncthreads();

    uint32_t qh[4][4], ql[4][4];
    {
        const int row16 = (lane & 7) | (((lane >> 3) & 1) << 3);
#pragma unroll
        for (int ds = 0; ds < 4; ds++) {
            const int colb = ((lane >> 4) << 4) + ds * 32;
            uint32_t off = swz128((uint32_t)(((wid * 16 + row16) << 7) + colb));
            ldsm4(qh[ds], sb + off);
            ldsm4(ql[ds], sb + 16384u + off);
        }
    }

    float accO[8][4];
#pragma unroll
    for (int i = 0; i < 8; i++)
#pragma unroll
        for (int j = 0; j < 4; j++) accO[i][j] = 0.0f;
    float rs0 = 0.0f, rs1 = 0.0f;

    const int rowB = (lane & 7) | ((lane >> 4) << 3);
    const int colBh = ((lane >> 3) & 1) << 4;
    const int rowV = lane & 15;
    const int colV = (lane >> 4) * 16;

    for (int t = 0; t < 32; t++) {
        if (t + 1 < 32) { issueKV(t + 1); CP_WAIT(1); }
        else            { CP_WAIT(0); }
        __syncthreads();
        const uint32_t st = sb + 32768u + (uint32_t)(t & 1) * 16384u;

        // S = (Qh + Ql) * Kh   (scale pre-folded into Q)
        float accS[8][4];
#pragma unroll
        for (int i = 0; i < 8; i++)
#pragma unroll
            for (int j = 0; j < 4; j++) accS[i][j] = 0.0f;

#pragma unroll
        for (int ds = 0; ds < 4; ds++) {
            const int colb = colBh + ds * 32;
#pragma unroll
            for (int p = 0; p < 4; p++) {
                uint32_t bh_[4];
                uint32_t off = swz128((uint32_t)(((p * 16 + rowB) << 7) + colb));
                ldsm4(bh_, st + off);
#pragma unroll
                for (int half = 0; half < 2; half++) {
                    const int nt = p * 2 + half;
                    mma_f16(accS[nt], qh[ds], &bh_[half * 2]);
                    mma_f16(accS[nt], ql[ds], &bh_[half * 2]);
                }
            }
        }

        // exp + rowsum, pack P to fp16 (single plane)
        uint32_t pk[8][2];
#pragma unroll
        for (int nt = 0; nt < 8; nt++) {
            float e0 = __expf(accS[nt][0]);
            float e1 = __expf(accS[nt][1]);
            float e2 = __expf(accS[nt][2]);
            float e3 = __expf(accS[nt][3]);
            rs0 += e0 + e1; rs1 += e2 + e3;
            pk[nt][0] = pack2h(e0, e1);
            pk[nt][1] = pack2h(e2, e3);
        }

        // O += P * Vh   (V natural via ldmatrix.trans)
#pragma unroll
        for (int p = 0; p < 4; p++) {
            uint32_t ah[4];
            ah[0] = pk[2*p][0];   ah[1] = pk[2*p][1];
            ah[2] = pk[2*p+1][0]; ah[3] = pk[2*p+1][1];
#pragma unroll
            for (int jj = 0; jj < 4; jj++) {
                uint32_t vh_[4];
                uint32_t off = swz128((uint32_t)(((p * 16 + rowV) << 7) + jj * 32 + colV));
                ldsm4t(vh_, st + 8192u + off);
#pragma unroll
                for (int half = 0; half < 2; half++)
                    mma_f16(accO[jj * 2 + half], ah, &vh_[half * 2]);
            }
        }
        __syncthreads();
    }

    rs0 += __shfl_xor_sync(0xffffffffu, rs0, 1);
    rs0 += __shfl_xor_sync(0xffffffffu, rs0, 2);
    rs1 += __shfl_xor_sync(0xffffffffu, rs1, 1);
    rs1 += __shfl_xor_sync(0xffffffffu, rs1, 2);
    const float inv0 = 1.0f / (1.0f + rs0);
    const float inv1 = 1.0f / (1.0f + rs1);

    const int b = bh >> 4, h = bh & 15;
    const int qA = q0 + wid * 16 + (lane >> 2);
#pragma unroll
    for (int half = 0; half < 2; half++) {
        const int q = qA + half * 8;
        const float inv = half ? inv1 : inv0;
        const size_t rowb = ((size_t)b * S_ + q) * D_ + h * HD_;
#pragma unroll
        for (int nt = 0; nt < 8; nt++) {
            const int col = nt * 8 + (lane & 3) * 2;
            *(uint32_t*)&CH[rowb + col] =
                pack2h(accO[nt][half * 2] * inv, accO[nt][half * 2 + 1] * inv);
        }
    }
}

// ---------------- host ----------------
extern "C" void kernel_launch(void* const* d_in, const int* in_sizes, int n_in,
                              void* d_out, int out_size)
{
    (void)in_sizes; (void)n_in; (void)out_size;
    const float* query = (const float*)d_in[0];
    const float* key   = (const float*)d_in[1];
    const float* value = (const float*)d_in[2];
    const float* Wq = (const float*)d_in[3];
    const float* bq = (const float*)d_in[4];
    const float* Wk = (const float*)d_in[5];
    const float* bk = (const float*)d_in[6];
    const float* Wv = (const float*)d_in[7];
    const float* bv = (const float*)d_in[8];
    const float* Wf = (const float*)d_in[9];
    const float* bf = (const float*)d_in[10];

    __half* G;
    cudaGetSymbolAddress((void**)&G, g_hf);

    const int n4 = (int)(SZX / 4);
    split_f32<<<n4 / 256, 256>>>(query, G + O_X,           G + O_X + SZX,     n4);
    split_f32<<<n4 / 256, 256>>>(key,   G + O_X + 2*SZX,   G + O_X + 3*SZX,   n4);
    split_f32<<<n4 / 256, 256>>>(value, G + O_X + 4*SZX,   G + O_X + 5*SZX,   n4);

    transpose_h<<<dim3(32, 32), 256>>>(Wq, G + O_W,          D_, D_);
    transpose_h<<<dim3(32, 32), 256>>>(Wk, G + O_W + SZW,    D_, D_);
    transpose_h<<<dim3(32, 32), 256>>>(Wv, G + O_W + 2*SZW,  D_, D_);
    transpose_h<<<dim3(8, 32),  256>>>(Wf, G + O_WF,         D_, OUT_);

    const int gsm = 65536;
    cudaFuncSetAttribute(proj_mma,  cudaFuncAttributeMaxDynamicSharedMemorySize, gsm);
    cudaFuncSetAttribute(final_mma, cudaFuncAttributeMaxDynamicSharedMemorySize, gsm);

    proj_mma<<<dim3(D_ / 128, M_ / 128, 3), 256, gsm>>>(G, bq, bk, bv);

    const int asm_ = 32768 + 2 * 16384;  // 65536
    cudaFuncSetAttribute(attn_mma, cudaFuncAttributeMaxDynamicSharedMemorySize, asm_);
    attn_mma<<<dim3(BH_, S_ / 128), 256, asm_>>>(
        G + O_QH, G + O_QL, G + O_KH, G + O_VH, G + O_CH);

    final_mma<<<dim3(OUT_ / 128, M_ / 128), 256, gsm>>>(
        G + O_CH, G + O_WF, bf, (float*)d_out);
}

// round 9
// speedup vs baseline: 8.7022x; 1.5051x over previous
#include <cuda_runtime.h>
#include <cuda_fp16.h>
#include <cstdint>

#define B_ 4
#define S_ 2048
#define D_ 1024
#define H_ 16
#define HD_ 64
#define OUT_ 256
#define M_ (B_*S_)
#define BH_ (B_*H_)

static constexpr size_t SZX = (size_t)M_ * D_;
static constexpr size_t SZW = (size_t)D_ * D_;
static constexpr size_t SZF = (size_t)D_ * OUT_;

static constexpr size_t O_X   = 0;                      // [Xq,Xk,Xv] hi, stride SZX
static constexpr size_t O_W   = O_X + 3 * SZX;          // [Wq,Wk,Wv]^T, stride SZW
static constexpr size_t O_WF  = O_W + 3 * SZW;
static constexpr size_t O_QH  = O_WF + SZF;
static constexpr size_t O_KH  = O_QH + SZX;
static constexpr size_t O_VH  = O_KH + SZX;
static constexpr size_t O_CH  = O_VH + SZX;
static constexpr size_t TOTAL_HF = O_CH + SZX;

__device__ __half g_hf[TOTAL_HF];

// ---------------- helpers ----------------
__device__ __forceinline__ uint32_t smem_u32(const void* p) {
    uint32_t a;
    asm("{ .reg .u64 t; cvta.to.shared.u64 t, %1; cvt.u32.u64 %0, t; }" : "=r"(a) : "l"(p));
    return a;
}
__device__ __forceinline__ void ldsm4(uint32_t* r, uint32_t a) {
    asm volatile("ldmatrix.sync.aligned.m8n8.x4.shared.b16 {%0,%1,%2,%3}, [%4];"
        : "=r"(r[0]), "=r"(r[1]), "=r"(r[2]), "=r"(r[3]) : "r"(a));
}
__device__ __forceinline__ void ldsm4t(uint32_t* r, uint32_t a) {
    asm volatile("ldmatrix.sync.aligned.m8n8.x4.trans.shared.b16 {%0,%1,%2,%3}, [%4];"
        : "=r"(r[0]), "=r"(r[1]), "=r"(r[2]), "=r"(r[3]) : "r"(a));
}
__device__ __forceinline__ void mma_f16(float* d, const uint32_t* a, const uint32_t* b) {
    asm volatile("mma.sync.aligned.m16n8k16.row.col.f32.f16.f16.f32 "
        "{%0,%1,%2,%3}, {%4,%5,%6,%7}, {%8,%9}, {%0,%1,%2,%3};"
        : "+f"(d[0]), "+f"(d[1]), "+f"(d[2]), "+f"(d[3])
        : "r"(a[0]), "r"(a[1]), "r"(a[2]), "r"(a[3]), "r"(b[0]), "r"(b[1]));
}
__device__ __forceinline__ void cpa16(uint32_t dst, const void* src) {
    asm volatile("cp.async.cg.shared.global [%0], [%1], 16;" :: "r"(dst), "l"(src));
}
#define CP_COMMIT() asm volatile("cp.async.commit_group;" ::: "memory")
#define CP_WAIT(n)  asm volatile("cp.async.wait_group %0;" :: "n"(n) : "memory")

__device__ __forceinline__ uint32_t swz128(uint32_t o) { return o ^ ((o >> 3) & 0x70); }
__device__ __forceinline__ uint32_t pack2h(float a, float b) {
    __half2 t = __floats2half2_rn(a, b);
    return *(uint32_t*)&t;
}

// ---------------- conversions ----------------
// all three inputs -> fp16 hi planes (grid.y = input index)
__global__ void cvt3_h(const float* __restrict__ q, const float* __restrict__ k,
                       const float* __restrict__ v, __half* __restrict__ G, int n4) {
    const int z = blockIdx.y;
    const float* x = (z == 0) ? q : (z == 1) ? k : v;
    __half* hi = G + O_X + (size_t)z * SZX;
    int i = blockIdx.x * blockDim.x + threadIdx.x;
    if (i >= n4) return;
    float4 vv = ((const float4*)x)[i];
    ((uint32_t*)hi)[i*2]   = pack2h(vv.x, vv.y);
    ((uint32_t*)hi)[i*2+1] = pack2h(vv.z, vv.w);
}

// W [K][N] -> W^T [N][K] fp16 (grid.z = weight index)
__global__ void transpose3_h(const float* __restrict__ Wq, const float* __restrict__ Wk,
                             const float* __restrict__ Wv, __half* __restrict__ G) {
    __shared__ float t[32][33];
    const int z = blockIdx.z;
    const float* W = (z == 0) ? Wq : (z == 1) ? Wk : Wv;
    __half* Th = G + O_W + (size_t)z * SZW;
    const int n0 = blockIdx.x * 32, k0 = blockIdx.y * 32;
    const int tx = threadIdx.x & 31, ty = threadIdx.x >> 5;
#pragma unroll
    for (int i = 0; i < 32; i += 8)
        t[ty + i][tx] = W[(size_t)(k0 + ty + i) * D_ + n0 + tx];
    __syncthreads();
#pragma unroll
    for (int i = 0; i < 32; i += 8)
        Th[(size_t)(n0 + ty + i) * D_ + k0 + tx] = __float2half_rn(t[tx][ty + i]);
}

__global__ void transpose_h(const float* __restrict__ W, __half* __restrict__ Th,
                            int Kdim, int Ndim) {
    __shared__ float t[32][33];
    const int n0 = blockIdx.x * 32, k0 = blockIdx.y * 32;
    const int tx = threadIdx.x & 31, ty = threadIdx.x >> 5;
#pragma unroll
    for (int i = 0; i < 32; i += 8)
        t[ty + i][tx] = W[(size_t)(k0 + ty + i) * Ndim + n0 + tx];
    __syncthreads();
#pragma unroll
    for (int i = 0; i < 32; i += 8)
        Th[(size_t)(n0 + ty + i) * Kdim + k0 + tx] = __float2half_rn(t[tx][ty + i]);
}

// ---------------- GEMM mainloop: acc += A[128,1024] @ B[128 rows,1024]^T -----
__device__ __forceinline__ void gemm_body(
    float acc[2][8][4], const __half* A, const __half* Bh,
    uint32_t sb, int m0, int n0, int tid, int wr, int wc, int lane)
{
    auto issue = [&](int c) {
        const int kk = c * 64;
        const uint32_t dA = sb + (uint32_t)(c & 1) * 32768u;
        const uint32_t dB = dA + 16384u;
#pragma unroll
        for (int i = 0; i < 4; i++) {
            int fidx = tid + i * 256;
            int row = fidx >> 3, cc = fidx & 7;
            uint32_t off = swz128((uint32_t)(row * 128 + cc * 16));
            cpa16(dA + off, A  + (size_t)(m0 + row) * 1024 + kk + cc * 8);
            cpa16(dB + off, Bh + (size_t)(n0 + row) * 1024 + kk + cc * 8);
        }
        CP_COMMIT();
    };

    issue(0);
    for (int c = 0; c < 16; c++) {
        if (c + 1 < 16) { issue(c + 1); CP_WAIT(1); }
        else            { CP_WAIT(0); }
        __syncthreads();
        const uint32_t sA = sb + (uint32_t)(c & 1) * 32768u;
        const uint32_t sB = sA + 16384u;
#pragma unroll
        for (int s = 0; s < 4; s++) {
            uint32_t aF[2][4], bF[4][4];
            {
                const int row16 = (lane & 7) | (((lane >> 3) & 1) << 3);
                const int colb = ((lane >> 4) << 4) + s * 32;
#pragma unroll
                for (int mt = 0; mt < 2; mt++)
                    ldsm4(aF[mt], sA + swz128((uint32_t)(((wr * 32 + mt * 16 + row16) << 7) + colb)));
            }
            {
                const int row16 = (lane & 7) | ((lane >> 4) << 3);
                const int colb = (((lane >> 3) & 1) << 4) + s * 32;
#pragma unroll
                for (int p = 0; p < 4; p++)
                    ldsm4(bF[p], sB + swz128((uint32_t)(((wc * 64 + p * 16 + row16) << 7) + colb)));
            }
#pragma unroll
            for (int mt = 0; mt < 2; mt++)
#pragma unroll
                for (int nt = 0; nt < 8; nt++)
                    mma_f16(acc[mt][nt], aF[mt], &bF[nt >> 1][(nt & 1) * 2]);
        }
        __syncthreads();
    }
}

// ---------------- merged QKV projection (grid.z = 0:Q, 1:K, 2:V) -------------
__global__ void __launch_bounds__(256, 2) proj_mma(
    __half* __restrict__ G,
    const float* __restrict__ bq, const float* __restrict__ bk,
    const float* __restrict__ bv)
{
    extern __shared__ __align__(1024) char sm[];
    const uint32_t sb = smem_u32(sm);
    const int tid = threadIdx.x, wid = tid >> 5, lane = tid & 31;
    const int m0 = blockIdx.y * 128, n0 = blockIdx.x * 128;
    const int z = blockIdx.z;
    const int wr = wid >> 1, wc = wid & 1;

    const __half* A  = G + O_X + (size_t)z * SZX;
    const __half* Bh = G + O_W + (size_t)z * SZW;
    const float* bias = (z == 0) ? bq : (z == 1) ? bk : bv;

    float acc[2][8][4];
#pragma unroll
    for (int i = 0; i < 2; i++)
#pragma unroll
        for (int j = 0; j < 8; j++)
#pragma unroll
            for (int q = 0; q < 4; q++) acc[i][j][q] = 0.0f;

    gemm_body(acc, A, Bh, sb, m0, n0, tid, wr, wc, lane);

    __half* Oh = (z == 0) ? (G + O_QH) : (z == 1) ? (G + O_KH) : (G + O_VH);
    const float scale = (z == 0) ? 0.125f : 1.0f;

#pragma unroll
    for (int mt = 0; mt < 2; mt++) {
        const int r0 = m0 + wr * 32 + mt * 16 + (lane >> 2);
#pragma unroll
        for (int half = 0; half < 2; half++) {
            const int m = r0 + half * 8;
            const int b = m >> 11, s = m & 2047;
#pragma unroll
            for (int nt = 0; nt < 8; nt++) {
                const int n = n0 + wc * 64 + nt * 8 + (lane & 3) * 2;
                float v0 = (acc[mt][nt][half * 2]     + __ldg(&bias[n]))     * scale;
                float v1 = (acc[mt][nt][half * 2 + 1] + __ldg(&bias[n + 1])) * scale;
                const int h = n >> 6, hd = n & 63;
                size_t addr = (((size_t)b * H_ + h) * S_ + s) * HD_ + hd;
                *(uint32_t*)&Oh[addr] = pack2h(v0, v1);
            }
        }
    }
}

// ---------------- final GEMM: out = Ch @ Wf^T + bf (fp32 out) ----------------
__global__ void __launch_bounds__(256, 2) final_mma(
    const __half* __restrict__ Ch, const __half* __restrict__ WfT,
    const float* __restrict__ bias, float* __restrict__ Of)
{
    extern __shared__ __align__(1024) char sm[];
    const uint32_t sb = smem_u32(sm);
    const int tid = threadIdx.x, wid = tid >> 5, lane = tid & 31;
    const int m0 = blockIdx.y * 128, n0 = blockIdx.x * 128;
    const int wr = wid >> 1, wc = wid & 1;

    float acc[2][8][4];
#pragma unroll
    for (int i = 0; i < 2; i++)
#pragma unroll
        for (int j = 0; j < 8; j++)
#pragma unroll
            for (int q = 0; q < 4; q++) acc[i][j][q] = 0.0f;

    gemm_body(acc, Ch, WfT, sb, m0, n0, tid, wr, wc, lane);

#pragma unroll
    for (int mt = 0; mt < 2; mt++) {
        const int r0 = m0 + wr * 32 + mt * 16 + (lane >> 2);
#pragma unroll
        for (int half = 0; half < 2; half++) {
            const int m = r0 + half * 8;
#pragma unroll
            for (int nt = 0; nt < 8; nt++) {
                const int n = n0 + wc * 64 + nt * 8 + (lane & 3) * 2;
                float2 o;
                o.x = acc[mt][nt][half * 2]     + __ldg(&bias[n]);
                o.y = acc[mt][nt][half * 2 + 1] + __ldg(&bias[n + 1]);
                *(float2*)&Of[(size_t)m * OUT_ + n] = o;
            }
        }
    }
}

// ---------------- attention (single-plane Q/K/V/P) ----------------
// smem: Qh 0..16K; stage st = 16K + (t&1)*16K: Kh +0, Vh +8K.  total 48KB
__global__ void __launch_bounds__(256, 2) attn_mma(
    const __half* __restrict__ QH, const __half* __restrict__ KH,
    const __half* __restrict__ VH, __half* __restrict__ CH)
{
    extern __shared__ __align__(1024) char sm[];
    const uint32_t sb = smem_u32(sm);
    const int tid = threadIdx.x, wid = tid >> 5, lane = tid & 31;
    const int bh = blockIdx.x, q0 = blockIdx.y * 128;
    const size_t baseQ = (size_t)bh * S_ * HD_ + (size_t)q0 * HD_;
    const size_t baseK = (size_t)bh * S_ * HD_;

    auto issueKV = [&](int t) {
        const uint32_t st = sb + 16384u + (uint32_t)(t & 1) * 16384u;
#pragma unroll
        for (int i = 0; i < 2; i++) {
            int fidx = tid + i * 256;
            int r = fidx >> 3, cc = fidx & 7;
            uint32_t off = swz128((uint32_t)(r * 128 + cc * 16));
            const size_t src = baseK + (size_t)(t * 64 + r) * 64 + cc * 8;
            cpa16(st + off,         KH + src);
            cpa16(st + 8192u + off, VH + src);
        }
        CP_COMMIT();
    };

#pragma unroll
    for (int i = 0; i < 4; i++) {
        int fidx = tid + i * 256;
        int row = fidx >> 3, cc = fidx & 7;
        uint32_t off = swz128((uint32_t)(row * 128 + cc * 16));
        cpa16(sb + off, QH + baseQ + (size_t)row * 64 + cc * 8);
    }
    CP_COMMIT();
    issueKV(0);
    CP_WAIT(1);
    __syncthreads();

    uint32_t qh[4][4];
    {
        const int row16 = (lane & 7) | (((lane >> 3) & 1) << 3);
#pragma unroll
        for (int ds = 0; ds < 4; ds++) {
            const int colb = ((lane >> 4) << 4) + ds * 32;
            uint32_t off = swz128((uint32_t)(((wid * 16 + row16) << 7) + colb));
            ldsm4(qh[ds], sb + off);
        }
    }

    float accO[8][4];
#pragma unroll
    for (int i = 0; i < 8; i++)
#pragma unroll
        for (int j = 0; j < 4; j++) accO[i][j] = 0.0f;
    float rs0 = 0.0f, rs1 = 0.0f;

    const int rowB = (lane & 7) | ((lane >> 4) << 3);
    const int colBh = ((lane >> 3) & 1) << 4;
    const int rowV = lane & 15;
    const int colV = (lane >> 4) * 16;

    for (int t = 0; t < 32; t++) {
        if (t + 1 < 32) { issueKV(t + 1); CP_WAIT(1); }
        else            { CP_WAIT(0); }
        __syncthreads();
        const uint32_t st = sb + 16384u + (uint32_t)(t & 1) * 16384u;

        // S = Qh * Kh  (scale pre-folded into Q)
        float accS[8][4];
#pragma unroll
        for (int i = 0; i < 8; i++)
#pragma unroll
            for (int j = 0; j < 4; j++) accS[i][j] = 0.0f;

#pragma unroll
        for (int ds = 0; ds < 4; ds++) {
            const int colb = colBh + ds * 32;
#pragma unroll
            for (int p = 0; p < 4; p++) {
                uint32_t bh_[4];
                uint32_t off = swz128((uint32_t)(((p * 16 + rowB) << 7) + colb));
                ldsm4(bh_, st + off);
#pragma unroll
                for (int half = 0; half < 2; half++)
                    mma_f16(accS[p * 2 + half], qh[ds], &bh_[half * 2]);
            }
        }

        // exp + rowsum, pack P single-plane fp16
        uint32_t pk[8][2];
#pragma unroll
        for (int nt = 0; nt < 8; nt++) {
            float e0 = __expf(accS[nt][0]);
            float e1 = __expf(accS[nt][1]);
            float e2 = __expf(accS[nt][2]);
            float e3 = __expf(accS[nt][3]);
            rs0 += e0 + e1; rs1 += e2 + e3;
            pk[nt][0] = pack2h(e0, e1);
            pk[nt][1] = pack2h(e2, e3);
        }

        // O += P * Vh
#pragma unroll
        for (int p = 0; p < 4; p++) {
            uint32_t ah[4];
            ah[0] = pk[2*p][0];   ah[1] = pk[2*p][1];
            ah[2] = pk[2*p+1][0]; ah[3] = pk[2*p+1][1];
#pragma unroll
            for (int jj = 0; jj < 4; jj++) {
                uint32_t vh_[4];
                uint32_t off = swz128((uint32_t)(((p * 16 + rowV) << 7) + jj * 32 + colV));
                ldsm4t(vh_, st + 8192u + off);
#pragma unroll
                for (int half = 0; half < 2; half++)
                    mma_f16(accO[jj * 2 + half], ah, &vh_[half * 2]);
            }
        }
        __syncthreads();
    }

    rs0 += __shfl_xor_sync(0xffffffffu, rs0, 1);
    rs0 += __shfl_xor_sync(0xffffffffu, rs0, 2);
    rs1 += __shfl_xor_sync(0xffffffffu, rs1, 1);
    rs1 += __shfl_xor_sync(0xffffffffu, rs1, 2);
    const float inv0 = 1.0f / (1.0f + rs0);
    const float inv1 = 1.0f / (1.0f + rs1);

    const int b = bh >> 4, h = bh & 15;
    const int qA = q0 + wid * 16 + (lane >> 2);
#pragma unroll
    for (int half = 0; half < 2; half++) {
        const int q = qA + half * 8;
        const float inv = half ? inv1 : inv0;
        const size_t rowb = ((size_t)b * S_ + q) * D_ + h * HD_;
#pragma unroll
        for (int nt = 0; nt < 8; nt++) {
            const int col = nt * 8 + (lane & 3) * 2;
            *(uint32_t*)&CH[rowb + col] =
                pack2h(accO[nt][half * 2] * inv, accO[nt][half * 2 + 1] * inv);
        }
    }
}

// ---------------- host ----------------
extern "C" void kernel_launch(void* const* d_in, const int* in_sizes, int n_in,
                              void* d_out, int out_size)
{
    (void)in_sizes; (void)n_in; (void)out_size;
    const float* query = (const float*)d_in[0];
    const float* key   = (const float*)d_in[1];
    const float* value = (const float*)d_in[2];
    const float* Wq = (const float*)d_in[3];
    const float* bq = (const float*)d_in[4];
    const float* Wk = (const float*)d_in[5];
    const float* bk = (const float*)d_in[6];
    const float* Wv = (const float*)d_in[7];
    const float* bv = (const float*)d_in[8];
    const float* Wf = (const float*)d_in[9];
    const float* bf = (const float*)d_in[10];

    __half* G;
    cudaGetSymbolAddress((void**)&G, g_hf);

    const int n4 = (int)(SZX / 4);
    cvt3_h<<<dim3(n4 / 256, 3), 256>>>(query, key, value, G, n4);
    transpose3_h<<<dim3(32, 32, 3), 256>>>(Wq, Wk, Wv, G);
    transpose_h<<<dim3(8, 32), 256>>>(Wf, G + O_WF, D_, OUT_);

    const int gsm = 65536;
    cudaFuncSetAttribute(proj_mma,  cudaFuncAttributeMaxDynamicSharedMemorySize, gsm);
    cudaFuncSetAttribute(final_mma, cudaFuncAttributeMaxDynamicSharedMemorySize, gsm);

    proj_mma<<<dim3(D_ / 128, M_ / 128, 3), 256, gsm>>>(G, bq, bk, bv);

    const int asm_ = 16384 + 2 * 16384;  // 49152
    cudaFuncSetAttribute(attn_mma, cudaFuncAttributeMaxDynamicSharedMemorySize, asm_);
    attn_mma<<<dim3(BH_, S_ / 128), 256, asm_>>>(
        G + O_QH, G + O_KH, G + O_VH, G + O_CH);

    final_mma<<<dim3(OUT_ / 128, M_ / 128), 256, gsm>>>(
        G + O_CH, G + O_WF, bf, (float*)d_out);
}